// round 10
// baseline (speedup 1.0000x reference)
#include <cuda_runtime.h>
#include <math.h>

#define N_NODES 25600
#define N_EDGES 204800
#define ETOT    (N_EDGES + N_NODES)   // 230400
#define IN_CH   6
#define HID     64
#define HEADS   4
#define C1      (HEADS*HID)           // 256
#define G_GRAPHS 512
#define T_STEPS  50
#define OUT_DIM  30
#define NEG_SLOPE 0.2f
#define BN_INV 0.9999950000374996f    // 1/sqrt(1+1e-5)

// ---------------- scratch ----------------
__device__ float g_wsrc[24];                  // [k][h]
__device__ float g_wdst[24];
__device__ __align__(16) float g_x8[N_NODES*8];       // padded x rows
__device__ __align__(16) float g_asrc1[N_NODES*4];
__device__ __align__(16) float g_adst1[N_NODES*4];
__device__ __align__(16) float g_xagg[N_NODES*32];    // 4 heads x [x0..x5, denom, 0]
__device__ __align__(16) float g_hproj2[N_NODES*HID];
__device__ float g_asrc2[N_NODES];
__device__ float g_adst2[N_NODES];
__device__ float g_denom2[N_NODES];
__device__ __align__(16) float g_accum2[N_NODES*HID];
__device__ __align__(16) float g_xgates[N_NODES*C1];  // (t, g, 256)

// ---------------- helpers ----------------
__device__ __forceinline__ float lrelu(float v) { return v > 0.f ? v : NEG_SLOPE*v; }
__device__ __forceinline__ float eluf(float v)  { return v > 0.f ? v : (__expf(v) - 1.f); }
__device__ __forceinline__ float sigf(float v)  { return 1.f/(1.f+expf(-v)); }

__device__ __forceinline__ void redAdd4(float* addr, float a, float b, float c, float d) {
    asm volatile("red.global.add.v4.f32 [%0], {%1,%2,%3,%4};"
                 :: "l"(addr), "f"(a), "f"(b), "f"(c), "f"(d) : "memory");
}
__device__ __forceinline__ void ffma2(unsigned long long& d, unsigned long long a,
                                      unsigned long long b) {
    asm("fma.rn.f32x2 %0, %1, %2, %0;" : "+l"(d) : "l"(a), "l"(b));
}
__device__ __forceinline__ unsigned long long pk(float a, float b) {
    unsigned long long r;
    asm("mov.b64 %0, {%1, %2};" : "=l"(r) : "f"(a), "f"(b));
    return r;
}
__device__ __forceinline__ float2 unpk(unsigned long long v) {
    float2 r;
    asm("mov.b64 {%0, %1}, %2;" : "=f"(r.x), "=f"(r.y) : "l"(v));
    return r;
}

// ---------------- kernels ----------------
__global__ void k_pre1(const float* __restrict__ W1, const float* __restrict__ as1,
                       const float* __restrict__ ad1) {
    int t = threadIdx.x;
    if (t < 24) {
        int k = t >> 2, h = t & 3;
        float s = 0.f;
        for (int c = 0; c < 64; c++) s += W1[k*C1 + h*64 + c] * as1[h*64 + c];
        g_wsrc[t] = s;
    } else if (t >= 32 && t < 56) {
        int i = t - 32, k = i >> 2, h = i & 3;
        float s = 0.f;
        for (int c = 0; c < 64; c++) s += W1[k*C1 + h*64 + c] * ad1[h*64 + c];
        g_wdst[i] = s;
    }
}

__global__ void k_att1(const float* __restrict__ x) {
    int n = blockIdx.x*blockDim.x + threadIdx.x;
    if (n >= N_NODES) return;
    float2 xa = *(const float2*)&x[n*6];
    float2 xb = *(const float2*)&x[n*6 + 2];
    float2 xc = *(const float2*)&x[n*6 + 4];
    float xv[6] = {xa.x, xa.y, xb.x, xb.y, xc.x, xc.y};
    float s[4] = {0,0,0,0}, d[4] = {0,0,0,0};
    #pragma unroll
    for (int k = 0; k < 6; k++) {
        #pragma unroll
        for (int h = 0; h < 4; h++) {
            s[h] += xv[k]*g_wsrc[k*4+h];
            d[h] += xv[k]*g_wdst[k*4+h];
        }
    }
    *(float4*)&g_asrc1[n*4] = make_float4(s[0],s[1],s[2],s[3]);
    *(float4*)&g_adst1[n*4] = make_float4(d[0],d[1],d[2],d[3]);
    *(float4*)&g_x8[n*8]     = make_float4(xv[0],xv[1],xv[2],xv[3]);
    *(float4*)&g_x8[n*8 + 4] = make_float4(xv[4],xv[5],0.f,0.f);
}

__global__ void k_esum1(const int* __restrict__ ei) {
    int e = blockIdx.x*blockDim.x + threadIdx.x;
    if (e >= ETOT) return;
    int s, d;
    if (e < N_EDGES) { s = ei[e]; d = ei[N_EDGES + e]; } else { s = d = e - N_EDGES; }
    float4 as = *(const float4*)&g_asrc1[s*4];
    float4 ad = *(const float4*)&g_adst1[d*4];
    float ex[4];
    ex[0] = expf(lrelu(as.x + ad.x));
    ex[1] = expf(lrelu(as.y + ad.y));
    ex[2] = expf(lrelu(as.z + ad.z));
    ex[3] = expf(lrelu(as.w + ad.w));
    float4 xa = *(const float4*)&g_x8[s*8];
    float4 xb = *(const float4*)&g_x8[s*8 + 4];
    float* base = &g_xagg[d*32];
    #pragma unroll
    for (int h = 0; h < 4; h++) {
        float w = ex[h];
        redAdd4(base + h*8,     w*xa.x, w*xa.y, w*xa.z, w*xa.w);
        redAdd4(base + h*8 + 4, w*xb.x, w*xb.y, w,      0.f);
    }
}

// fused GAT2 projection: two-phase.
// Phase1: h1[32 nodes][256 k] staged in smem (computed once per element).
// Phase2: thread = (node, 8-col group); per k: 1 LDS h + 2 broadcast LDS.128 W + 4 FFMA2.
#define P2N 32
#define H1STR 261
__global__ void __launch_bounds__(256, 2) k_proj2f(
        const float* __restrict__ W1, const float* __restrict__ b1,
        const float* __restrict__ g1, const float* __restrict__ be1,
        const float* __restrict__ W2,
        const float* __restrict__ as2, const float* __restrict__ ad2) {
    extern __shared__ float sm[];
    float* sW2  = sm;                    // [256][64] = 16384
    float* sW1p = sm + 16384;            // [256][8]: {w0..w5, A, C} = 2048
    float* h1s  = sW1p + 2048;           // [32][261] = 8352
    float* sAs  = h1s + P2N*H1STR;       // 64
    float* sAd  = sAs + 64;              // 64
    float* sS   = sAd + 64;              // 256
    float* sD   = sS + 256;              // 256
    int t = threadIdx.x;
    int nbase = blockIdx.x * P2N;

    for (int i = t; i < 16384; i += 256) sW2[i] = W2[i];
    for (int i = t; i < 2048; i += 256) {
        int c = i >> 3, r = i & 7;
        float v;
        if (r < 6)       v = W1[r*C1 + c];
        else if (r == 6) v = g1[c]*BN_INV;
        else { float A = g1[c]*BN_INV; v = A*b1[c] + be1[c]; }
        sW1p[i] = v;
    }
    if (t < 64)            sAs[t] = as2[t];
    else if (t < 128)      sAd[t-64] = ad2[t-64];
    __syncthreads();

    int nl = t & 31;                 // node (phase1 & phase2)
    int q  = t >> 5;                 // 0..7: 32-col chunk (p1) / 8-col group (p2)
    int n  = nbase + nl;

    // xagg row, pre-scaled by 1/denom per head (redundant per 8 threads; L1-cached)
    float xr[24];
    #pragma unroll
    for (int h = 0; h < 4; h++) {
        float4 v0 = *(const float4*)&g_xagg[n*32 + h*8];
        float4 v1 = *(const float4*)&g_xagg[n*32 + h*8 + 4];
        float inv = 1.f / v1.z;      // slot 6 = denom
        xr[h*6+0] = v0.x*inv; xr[h*6+1] = v0.y*inv; xr[h*6+2] = v0.z*inv;
        xr[h*6+3] = v0.w*inv; xr[h*6+4] = v1.x*inv; xr[h*6+5] = v1.y*inv;
    }

    // phase 1: h1 cols [q*32, q*32+32) for node nl
    #pragma unroll 4
    for (int c2 = 0; c2 < 32; c2++) {
        int c = q*32 + c2;
        float4 wa = *(const float4*)&sW1p[c*8];
        float4 wb = *(const float4*)&sW1p[c*8 + 4];
        int h = c >> 6;
        float dot = xr[h*6+0]*wa.x + xr[h*6+1]*wa.y + xr[h*6+2]*wa.z
                  + xr[h*6+3]*wa.w + xr[h*6+4]*wb.x + xr[h*6+5]*wb.y;
        h1s[nl*H1STR + c] = eluf(dot*wb.z + wb.w);
    }
    __syncthreads();

    // phase 2: node nl, cols [q*8, q*8+8)
    int j0 = q*8;
    unsigned long long acc2[4];
    acc2[0] = 0ull; acc2[1] = 0ull; acc2[2] = 0ull; acc2[3] = 0ull;
    const float* hrow = &h1s[nl*H1STR];
    #pragma unroll 8
    for (int k = 0; k < 256; k++) {
        float v = hrow[k];
        unsigned long long vv = pk(v, v);
        ulonglong2 w01 = *(const ulonglong2*)&sW2[k*64 + j0];
        ulonglong2 w23 = *(const ulonglong2*)&sW2[k*64 + j0 + 4];
        ffma2(acc2[0], vv, w01.x);
        ffma2(acc2[1], vv, w01.y);
        ffma2(acc2[2], vv, w23.x);
        ffma2(acc2[3], vv, w23.y);
    }

    float2 u0 = unpk(acc2[0]), u1 = unpk(acc2[1]);
    float2 u2 = unpk(acc2[2]), u3 = unpk(acc2[3]);
    *(float4*)&g_hproj2[n*64 + j0]     = make_float4(u0.x, u0.y, u1.x, u1.y);
    *(float4*)&g_hproj2[n*64 + j0 + 4] = make_float4(u2.x, u2.y, u3.x, u3.y);
    float s  = u0.x*sAs[j0]   + u0.y*sAs[j0+1] + u1.x*sAs[j0+2] + u1.y*sAs[j0+3]
             + u2.x*sAs[j0+4] + u2.y*sAs[j0+5] + u3.x*sAs[j0+6] + u3.y*sAs[j0+7];
    float dd = u0.x*sAd[j0]   + u0.y*sAd[j0+1] + u1.x*sAd[j0+2] + u1.y*sAd[j0+3]
             + u2.x*sAd[j0+4] + u2.y*sAd[j0+5] + u3.x*sAd[j0+6] + u3.y*sAd[j0+7];
    sS[nl*8 + q] = s;
    sD[nl*8 + q] = dd;
    __syncthreads();
    if (t < P2N) {
        float ss = 0.f, dd2 = 0.f;
        #pragma unroll
        for (int j = 0; j < 8; j++) { ss += sS[t*8 + j]; dd2 += sD[t*8 + j]; }
        g_asrc2[nbase + t] = ss;
        g_adst2[nbase + t] = dd2;
    }
}

// 8 threads/edge: denom += ex; accum2[dst] += ex*hproj2[src]
__global__ void k_esum2(const int* __restrict__ ei) {
    int gt = blockIdx.x*blockDim.x + threadIdx.x;
    int e = gt >> 3, q = gt & 7;
    if (e >= ETOT) return;
    int s, d;
    if (e < N_EDGES) { s = ei[e]; d = ei[N_EDGES + e]; } else { s = d = e - N_EDGES; }
    float ex = expf(lrelu(g_asrc2[s] + g_adst2[d]));
    if (q == 0) atomicAdd(&g_denom2[d], ex);
    int c = q*8;
    float4 v1 = *(const float4*)&g_hproj2[s*64 + c];
    float4 v2 = *(const float4*)&g_hproj2[s*64 + c + 4];
    redAdd4(&g_accum2[d*64 + c],     v1.x*ex, v1.y*ex, v1.z*ex, v1.w*ex);
    redAdd4(&g_accum2[d*64 + c + 4], v2.x*ex, v2.y*ex, v2.z*ex, v2.w*ex);
}

// fused: h2 staged once in smem; xgates = h2@Wih^T + biases (scattered).
// 32 nodes/block, 256 threads; thread = (node pair, 16-col group); 2n x 16c tile.
#define XGN 32
__global__ void __launch_bounds__(256, 3) k_xgates2(
        const float* __restrict__ Wih, const float* __restrict__ bih,
        const float* __restrict__ bhh, const float* __restrict__ b2,
        const float* __restrict__ g2, const float* __restrict__ be2,
        const int* __restrict__ batch, const int* __restrict__ ntime) {
    extern __shared__ float sm[];
    float* sWT   = sm;                 // [64 k][256 j] = Wih^T = 16384
    float* h2s   = sm + 16384;         // [32][65] = 2080
    float* sBias = h2s + 2080;         // 256
    float* sA2   = sBias + 256;        // 64
    float* sC2   = sA2 + 64;           // 64
    float* sInv  = sC2 + 64;           // 32
    int t = threadIdx.x;
    int nbase = blockIdx.x * XGN;

    for (int i = t; i < 16384; i += 256) {
        int j = i >> 6, k = i & 63;
        sWT[k*256 + j] = Wih[i];
    }
    if (t < 256) sBias[t] = bih[t] + bhh[t];
    if (t < 64) {
        float A = g2[t]*BN_INV;
        sA2[t] = A;
        sC2[t] = A*b2[t] + be2[t];
    } else if (t >= 128 && t < 160) {
        sInv[t-128] = 1.f / g_denom2[nbase + (t-128)];
    }
    __syncthreads();

    // stage h2 once
    for (int i = t; i < XGN*64; i += 256) {
        int nn = i >> 6, k = i & 63;
        float v = g_accum2[(nbase + nn)*64 + k] * sInv[nn];
        h2s[nn*65 + k] = eluf(v*sA2[k] + sC2[k]);
    }
    __syncthreads();

    int nl2 = t & 15;                  // node pair: nodes 2*nl2, 2*nl2+1
    int cg  = t >> 4;                  // 0..15 -> 16-col group
    int j0  = cg*16;

    unsigned long long a0[8], a1[8];
    #pragma unroll
    for (int j = 0; j < 8; j++) { a0[j] = 0ull; a1[j] = 0ull; }

    const float* h0 = &h2s[(2*nl2)*65];
    const float* h1r = &h2s[(2*nl2+1)*65];
    #pragma unroll 4
    for (int k = 0; k < 64; k++) {
        float v0 = h0[k], v1 = h1r[k];
        unsigned long long vv0 = pk(v0, v0), vv1 = pk(v1, v1);
        const float* wb = &sWT[k*256 + j0];
        ulonglong2 wA = *(const ulonglong2*)wb;
        ulonglong2 wB = *(const ulonglong2*)(wb + 4);
        ulonglong2 wC = *(const ulonglong2*)(wb + 8);
        ulonglong2 wD = *(const ulonglong2*)(wb + 12);
        ffma2(a0[0], vv0, wA.x); ffma2(a0[1], vv0, wA.y);
        ffma2(a0[2], vv0, wB.x); ffma2(a0[3], vv0, wB.y);
        ffma2(a0[4], vv0, wC.x); ffma2(a0[5], vv0, wC.y);
        ffma2(a0[6], vv0, wD.x); ffma2(a0[7], vv0, wD.y);
        ffma2(a1[0], vv1, wA.x); ffma2(a1[1], vv1, wA.y);
        ffma2(a1[2], vv1, wB.x); ffma2(a1[3], vv1, wB.y);
        ffma2(a1[4], vv1, wC.x); ffma2(a1[5], vv1, wC.y);
        ffma2(a1[6], vv1, wD.x); ffma2(a1[7], vv1, wD.y);
    }

    #pragma unroll
    for (int node = 0; node < 2; node++) {
        unsigned long long* aa = node ? a1 : a0;
        int n = nbase + 2*nl2 + node;
        int dest = (ntime[n]*G_GRAPHS + batch[n])*C1 + j0;
        #pragma unroll
        for (int w4 = 0; w4 < 4; w4++) {
            float2 ua = unpk(aa[2*w4]);
            float2 ub = unpk(aa[2*w4+1]);
            int j = j0 + w4*4;
            *(float4*)&g_xgates[dest + w4*4] =
                make_float4(ua.x+sBias[j],   ua.y+sBias[j+1],
                            ub.x+sBias[j+2], ub.y+sBias[j+3]);
        }
    }
}

// LSTM: 1 graph/block (512 blocks), Whh row in regs, xgates prefetch, fused FC.
__global__ void __launch_bounds__(256) k_lstm(
        const float* __restrict__ Whh, const float* __restrict__ Wfc,
        const float* __restrict__ bfc, float* __restrict__ out) {
    __shared__ float hhs[64];
    __shared__ float gates[C1];
    int t = threadIdx.x;
    int g = blockIdx.x;

    unsigned long long w2[32];
    const float4* wrow = (const float4*)(Whh + t*64);
    #pragma unroll
    for (int i = 0; i < 16; i++) {
        float4 w = wrow[i];
        w2[2*i]   = pk(w.x, w.y);
        w2[2*i+1] = pk(w.z, w.w);
    }
    if (t < 64) hhs[t] = 0.f;
    float c = 0.f;
    float xg_cur = g_xgates[g*C1 + t];
    __syncthreads();

    for (int step = 0; step < T_STEPS; step++) {
        float xg_next = 0.f;
        if (step + 1 < T_STEPS) xg_next = g_xgates[((step+1)*G_GRAPHS + g)*C1 + t];
        unsigned long long aA = 0ull, aB = 0ull;
        #pragma unroll
        for (int k2 = 0; k2 < 16; k2++) {
            ulonglong2 hv = *(const ulonglong2*)&hhs[k2*4];
            ffma2(aA, hv.x, w2[2*k2]);
            ffma2(aB, hv.y, w2[2*k2+1]);
        }
        float2 a = unpk(aA), b = unpk(aB);
        gates[t] = xg_cur + a.x + a.y + b.x + b.y;
        __syncthreads();
        if (t < 64) {
            float ig = gates[t],       fg = gates[64 + t];
            float gg = gates[128 + t], og = gates[192 + t];
            c = sigf(fg)*c + sigf(ig)*tanhf(gg);
            hhs[t] = sigf(og)*tanhf(c);
        }
        __syncthreads();
        xg_cur = xg_next;
    }
    if (t < OUT_DIM) {
        float acc = bfc[t];
        #pragma unroll 8
        for (int k = 0; k < 64; k++) acc += hhs[k] * Wfc[k*OUT_DIM + t];
        out[g*OUT_DIM + t] = acc;
    }
}

// ---------------- launch ----------------
static const int SMEM_P2 = (16384 + 2048 + P2N*H1STR + 64 + 64 + 256 + 256) * 4; // 109696 B
static const int SMEM_XG = (16384 + 2080 + 256 + 64 + 64 + 32) * 4;              // 75520 B

extern "C" void kernel_launch(void* const* d_in, const int* in_sizes, int n_in,
                              void* d_out, int out_size) {
    const float* x    = (const float*)d_in[0];
    const int*   ei   = (const int*)  d_in[1];
    const int*   batch= (const int*)  d_in[2];
    const int*   ntime= (const int*)  d_in[3];
    const float* W1   = (const float*)d_in[4];
    const float* as1  = (const float*)d_in[5];
    const float* ad1  = (const float*)d_in[6];
    const float* b1   = (const float*)d_in[7];
    const float* g1   = (const float*)d_in[8];
    const float* be1  = (const float*)d_in[9];
    const float* W2   = (const float*)d_in[10];
    const float* as2  = (const float*)d_in[11];
    const float* ad2  = (const float*)d_in[12];
    const float* b2   = (const float*)d_in[13];
    const float* g2   = (const float*)d_in[14];
    const float* be2  = (const float*)d_in[15];
    const float* Wih  = (const float*)d_in[16];
    const float* Whh  = (const float*)d_in[17];
    const float* bih  = (const float*)d_in[18];
    const float* bhh  = (const float*)d_in[19];
    const float* Wfc  = (const float*)d_in[20];
    const float* bfc  = (const float*)d_in[21];
    float* out = (float*)d_out;

    cudaFuncSetAttribute(k_proj2f,  cudaFuncAttributeMaxDynamicSharedMemorySize, SMEM_P2);
    cudaFuncSetAttribute(k_xgates2, cudaFuncAttributeMaxDynamicSharedMemorySize, SMEM_XG);

    void *p_xagg, *p_acc2, *p_den2;
    cudaGetSymbolAddress(&p_xagg, g_xagg);
    cudaGetSymbolAddress(&p_acc2, g_accum2);
    cudaGetSymbolAddress(&p_den2, g_denom2);
    cudaMemsetAsync(p_xagg, 0, sizeof(float)*N_NODES*32);
    cudaMemsetAsync(p_acc2, 0, sizeof(float)*N_NODES*HID);
    cudaMemsetAsync(p_den2, 0, sizeof(float)*N_NODES);

    k_pre1   <<<1, 64>>>(W1, as1, ad1);
    k_att1   <<<(N_NODES + 255)/256, 256>>>(x);
    k_esum1  <<<(ETOT + 255)/256, 256>>>(ei);
    k_proj2f <<<N_NODES/P2N, 256, SMEM_P2>>>(W1, b1, g1, be1, W2, as2, ad2);
    k_esum2  <<<(ETOT*8 + 255)/256, 256>>>(ei);
    k_xgates2<<<N_NODES/XGN, 256, SMEM_XG>>>(Wih, bih, bhh, b2, g2, be2, batch, ntime);
    k_lstm   <<<G_GRAPHS, 256>>>(Whh, Wfc, bfc, out);
}

// round 11
// speedup vs baseline: 1.3125x; 1.3125x over previous
#include <cuda_runtime.h>
#include <math.h>
#include <stdint.h>

#define N_NODES 25600
#define N_EDGES 204800
#define ETOT    (N_EDGES + N_NODES)   // 230400
#define IN_CH   6
#define HID     64
#define HEADS   4
#define C1      (HEADS*HID)           // 256
#define G_GRAPHS 512
#define T_STEPS  50
#define OUT_DIM  30
#define NEG_SLOPE 0.2f
#define BN_INV 0.9999950000374996f    // 1/sqrt(1+1e-5)

// ---------------- scratch ----------------
__device__ float g_wsrc[24];
__device__ float g_wdst[24];
__device__ __align__(16) float g_x8[N_NODES*8];
__device__ __align__(16) float g_asrc1[N_NODES*4];
__device__ __align__(16) float g_adst1[N_NODES*4];
__device__ __align__(16) float g_xagg[N_NODES*32];    // 4 heads x [x0..x5, denom, 0]
__device__ __align__(16) float g_hproj2[N_NODES*HID];
__device__ float g_asrc2[N_NODES];
__device__ float g_adst2[N_NODES];
__device__ float g_denom2[N_NODES];
__device__ __align__(16) float g_accum2[N_NODES*HID];
__device__ __align__(16) float g_xgates[N_NODES*C1];  // (t, g, 256)

// ---------------- helpers ----------------
__device__ __forceinline__ float lrelu(float v) { return v > 0.f ? v : NEG_SLOPE*v; }
__device__ __forceinline__ float eluf(float v)  { return v > 0.f ? v : (__expf(v) - 1.f); }
__device__ __forceinline__ float sigf(float v)  { return 1.f/(1.f+expf(-v)); }

__device__ __forceinline__ void redAdd4(float* addr, float a, float b, float c, float d) {
    asm volatile("red.global.add.v4.f32 [%0], {%1,%2,%3,%4};"
                 :: "l"(addr), "f"(a), "f"(b), "f"(c), "f"(d) : "memory");
}
__device__ __forceinline__ void ffma2(unsigned long long& d, unsigned long long a,
                                      unsigned long long b) {
    asm("fma.rn.f32x2 %0, %1, %2, %0;" : "+l"(d) : "l"(a), "l"(b));
}
__device__ __forceinline__ unsigned long long pk(float a, float b) {
    unsigned long long r;
    asm("mov.b64 %0, {%1, %2};" : "=l"(r) : "f"(a), "f"(b));
    return r;
}
__device__ __forceinline__ float2 unpk(unsigned long long v) {
    float2 r;
    asm("mov.b64 {%0, %1}, %2;" : "=f"(r.x), "=f"(r.y) : "l"(v));
    return r;
}
__device__ __forceinline__ uint32_t f2tf32(float v) {
    uint32_t r;
    asm("cvt.rna.tf32.f32 %0, %1;" : "=r"(r) : "f"(v));
    return r;
}
// m16n8k8 tf32 MMA, fp32 accumulate (in-place)
__device__ __forceinline__ void mma_tf32(float* d, const uint32_t* a, const uint32_t* b) {
    asm("mma.sync.aligned.m16n8k8.row.col.f32.tf32.tf32.f32 "
        "{%0,%1,%2,%3},{%4,%5,%6,%7},{%8,%9},{%0,%1,%2,%3};"
        : "+f"(d[0]), "+f"(d[1]), "+f"(d[2]), "+f"(d[3])
        : "r"(a[0]), "r"(a[1]), "r"(a[2]), "r"(a[3]), "r"(b[0]), "r"(b[1]));
}

// ---------------- kernels ----------------
__global__ void k_pre1(const float* __restrict__ W1, const float* __restrict__ as1,
                       const float* __restrict__ ad1) {
    int t = threadIdx.x;
    if (t < 24) {
        int k = t >> 2, h = t & 3;
        float s = 0.f;
        for (int c = 0; c < 64; c++) s += W1[k*C1 + h*64 + c] * as1[h*64 + c];
        g_wsrc[t] = s;
    } else if (t >= 32 && t < 56) {
        int i = t - 32, k = i >> 2, h = i & 3;
        float s = 0.f;
        for (int c = 0; c < 64; c++) s += W1[k*C1 + h*64 + c] * ad1[h*64 + c];
        g_wdst[i] = s;
    }
}

__global__ void k_att1(const float* __restrict__ x) {
    int n = blockIdx.x*blockDim.x + threadIdx.x;
    if (n >= N_NODES) return;
    float2 xa = *(const float2*)&x[n*6];
    float2 xb = *(const float2*)&x[n*6 + 2];
    float2 xc = *(const float2*)&x[n*6 + 4];
    float xv[6] = {xa.x, xa.y, xb.x, xb.y, xc.x, xc.y};
    float s[4] = {0,0,0,0}, d[4] = {0,0,0,0};
    #pragma unroll
    for (int k = 0; k < 6; k++) {
        #pragma unroll
        for (int h = 0; h < 4; h++) {
            s[h] += xv[k]*g_wsrc[k*4+h];
            d[h] += xv[k]*g_wdst[k*4+h];
        }
    }
    *(float4*)&g_asrc1[n*4] = make_float4(s[0],s[1],s[2],s[3]);
    *(float4*)&g_adst1[n*4] = make_float4(d[0],d[1],d[2],d[3]);
    *(float4*)&g_x8[n*8]     = make_float4(xv[0],xv[1],xv[2],xv[3]);
    *(float4*)&g_x8[n*8 + 4] = make_float4(xv[4],xv[5],0.f,0.f);
}

__global__ void k_esum1(const int* __restrict__ ei) {
    int e = blockIdx.x*blockDim.x + threadIdx.x;
    if (e >= ETOT) return;
    int s, d;
    if (e < N_EDGES) { s = ei[e]; d = ei[N_EDGES + e]; } else { s = d = e - N_EDGES; }
    float4 as = *(const float4*)&g_asrc1[s*4];
    float4 ad = *(const float4*)&g_adst1[d*4];
    float ex[4];
    ex[0] = expf(lrelu(as.x + ad.x));
    ex[1] = expf(lrelu(as.y + ad.y));
    ex[2] = expf(lrelu(as.z + ad.z));
    ex[3] = expf(lrelu(as.w + ad.w));
    float4 xa = *(const float4*)&g_x8[s*8];
    float4 xb = *(const float4*)&g_x8[s*8 + 4];
    float* base = &g_xagg[d*32];
    #pragma unroll
    for (int h = 0; h < 4; h++) {
        float w = ex[h];
        redAdd4(base + h*8,     w*xa.x, w*xa.y, w*xa.z, w*xa.w);
        redAdd4(base + h*8 + 4, w*xb.x, w*xb.y, w,      0.f);
    }
}

// fused GAT2 projection via tensor cores (tf32 MMA).
// Phase1: h1[32][256] staged as tf32 in smem. Phase2: m16n8k8 MMA. Epilogue: att2 dots.
#define P2N 32
#define H1STR 260          // (260*r + k) % 32 = (4r + k) % 32 -> conflict-free A frags
#define W2STR 66
__global__ void __launch_bounds__(256) k_proj2f(
        const float* __restrict__ W1, const float* __restrict__ b1,
        const float* __restrict__ g1, const float* __restrict__ be1,
        const float* __restrict__ W2,
        const float* __restrict__ as2, const float* __restrict__ ad2) {
    extern __shared__ float sm[];
    float* sW2t = sm;                      // [256][66] tf32 bits
    float* sW1p = sm + 256*W2STR;          // [256][8]: {w0..w5, A, C} f32
    float* h1s  = sW1p + 2048;             // [32][260] tf32 bits
    float* sAs  = h1s + P2N*H1STR;         // 64
    float* sAd  = sAs + 64;                // 64
    float* sS   = sAd + 64;                // 128 ([32 rows][4 nq])
    float* sD   = sS + 128;                // 128
    int t = threadIdx.x;
    int nbase = blockIdx.x * P2N;

    for (int i = t; i < 256*64; i += 256) {
        int k = i >> 6, j = i & 63;
        sW2t[k*W2STR + j] = __uint_as_float(f2tf32(W2[i]));
    }
    for (int i = t; i < 2048; i += 256) {
        int c = i >> 3, r = i & 7;
        float v;
        if (r < 6)       v = W1[r*C1 + c];
        else if (r == 6) v = g1[c]*BN_INV;
        else { float A = g1[c]*BN_INV; v = A*b1[c] + be1[c]; }
        sW1p[i] = v;
    }
    if (t < 64)            sAs[t] = as2[t];
    else if (t < 128)      sAd[t-64] = ad2[t-64];
    __syncthreads();

    // phase 1: h1 (tf32) — thread (nl, q) computes cols [q*32, q*32+32) of node nl
    {
        int nl = t & 31, q = t >> 5;
        int n  = nbase + nl;
        float xr[24];
        #pragma unroll
        for (int h = 0; h < 4; h++) {
            float4 v0 = *(const float4*)&g_xagg[n*32 + h*8];
            float4 v1 = *(const float4*)&g_xagg[n*32 + h*8 + 4];
            float inv = 1.f / v1.z;
            xr[h*6+0] = v0.x*inv; xr[h*6+1] = v0.y*inv; xr[h*6+2] = v0.z*inv;
            xr[h*6+3] = v0.w*inv; xr[h*6+4] = v1.x*inv; xr[h*6+5] = v1.y*inv;
        }
        #pragma unroll 4
        for (int c2 = 0; c2 < 32; c2++) {
            int c = q*32 + c2;
            float4 wa = *(const float4*)&sW1p[c*8];
            float4 wb = *(const float4*)&sW1p[c*8 + 4];
            int h = c >> 6;
            float dot = xr[h*6+0]*wa.x + xr[h*6+1]*wa.y + xr[h*6+2]*wa.z
                      + xr[h*6+3]*wa.w + xr[h*6+4]*wb.x + xr[h*6+5]*wb.y;
            h1s[nl*H1STR + c] = __uint_as_float(f2tf32(eluf(dot*wb.z + wb.w)));
        }
    }
    __syncthreads();

    // phase 2: MMA. warp w: m-tile mt=w&1 (16 nodes), n-quarter nq=w>>1 (16 cols = 2 n-tiles)
    const uint32_t* h1u = (const uint32_t*)h1s;
    const uint32_t* w2u = (const uint32_t*)sW2t;
    int w = t >> 5, l = t & 31;
    int g = l >> 2, c = l & 3;
    int mt = w & 1, nq = w >> 1;
    int r0 = mt*16 + g;

    float acc[2][4];
    #pragma unroll
    for (int nt = 0; nt < 2; nt++) { acc[nt][0]=0; acc[nt][1]=0; acc[nt][2]=0; acc[nt][3]=0; }

    const uint32_t* ap = h1u + r0*H1STR + c;
    #pragma unroll 4
    for (int ks = 0; ks < 32; ks++) {
        int kb = ks*8;
        uint32_t a[4];
        a[0] = ap[kb];
        a[1] = ap[kb + 8*H1STR];
        a[2] = ap[kb + 4];
        a[3] = ap[kb + 8*H1STR + 4];
        #pragma unroll
        for (int nt = 0; nt < 2; nt++) {
            int nb = nq*16 + nt*8;
            uint32_t b[2];
            b[0] = w2u[(kb + c)*W2STR + nb + g];
            b[1] = w2u[(kb + c + 4)*W2STR + nb + g];
            mma_tf32(acc[nt], a, b);
        }
    }

    // epilogue: store hproj2 + att2 partial dots
    float s0 = 0.f, d0 = 0.f, s1 = 0.f, d1 = 0.f;
    int n0 = nbase + r0, n1 = n0 + 8;
    #pragma unroll
    for (int nt = 0; nt < 2; nt++) {
        int col = nq*16 + nt*8 + 2*c;
        *(float2*)&g_hproj2[n0*64 + col] = make_float2(acc[nt][0], acc[nt][1]);
        *(float2*)&g_hproj2[n1*64 + col] = make_float2(acc[nt][2], acc[nt][3]);
        s0 += acc[nt][0]*sAs[col] + acc[nt][1]*sAs[col+1];
        d0 += acc[nt][0]*sAd[col] + acc[nt][1]*sAd[col+1];
        s1 += acc[nt][2]*sAs[col] + acc[nt][3]*sAs[col+1];
        d1 += acc[nt][2]*sAd[col] + acc[nt][3]*sAd[col+1];
    }
    #pragma unroll
    for (int m = 1; m < 4; m <<= 1) {
        s0 += __shfl_xor_sync(~0u, s0, m);
        d0 += __shfl_xor_sync(~0u, d0, m);
        s1 += __shfl_xor_sync(~0u, s1, m);
        d1 += __shfl_xor_sync(~0u, d1, m);
    }
    if (c == 0) {
        sS[r0*4 + nq] = s0; sD[r0*4 + nq] = d0;
        sS[(r0+8)*4 + nq] = s1; sD[(r0+8)*4 + nq] = d1;
    }
    __syncthreads();
    if (t < P2N) {
        float ss = sS[t*4] + sS[t*4+1] + sS[t*4+2] + sS[t*4+3];
        float dd = sD[t*4] + sD[t*4+1] + sD[t*4+2] + sD[t*4+3];
        g_asrc2[nbase + t] = ss;
        g_adst2[nbase + t] = dd;
    }
}

// 8 threads/edge: denom += ex; accum2[dst] += ex*hproj2[src]
__global__ void k_esum2(const int* __restrict__ ei) {
    int gt = blockIdx.x*blockDim.x + threadIdx.x;
    int e = gt >> 3, q = gt & 7;
    if (e >= ETOT) return;
    int s, d;
    if (e < N_EDGES) { s = ei[e]; d = ei[N_EDGES + e]; } else { s = d = e - N_EDGES; }
    float ex = expf(lrelu(g_asrc2[s] + g_adst2[d]));
    if (q == 0) atomicAdd(&g_denom2[d], ex);
    int c = q*8;
    float4 v1 = *(const float4*)&g_hproj2[s*64 + c];
    float4 v2 = *(const float4*)&g_hproj2[s*64 + c + 4];
    redAdd4(&g_accum2[d*64 + c],     v1.x*ex, v1.y*ex, v1.z*ex, v1.w*ex);
    redAdd4(&g_accum2[d*64 + c + 4], v2.x*ex, v2.y*ex, v2.z*ex, v2.w*ex);
}

// fused: h2 staged once as tf32; xgates = h2@Wih^T + biases via tf32 MMA (scattered rows).
#define XGN 64
#define H2STR 68           // (68*r + k) % 32 = (4r + k) % 32 -> conflict-free A frags
#define WTSTR 264          // (264*k + n) % 32 = (8k + n) % 32 -> conflict-free B frags
__global__ void __launch_bounds__(256) k_xgates2(
        const float* __restrict__ Wih, const float* __restrict__ bih,
        const float* __restrict__ bhh, const float* __restrict__ b2,
        const float* __restrict__ g2, const float* __restrict__ be2,
        const int* __restrict__ batch, const int* __restrict__ ntime) {
    extern __shared__ float sm[];
    float* sWT   = sm;                    // [64 k][264] tf32 bits (Wih^T)
    float* h2s   = sm + 64*WTSTR;         // [64][68] tf32 bits
    float* sBias = h2s + XGN*H2STR;       // 256
    float* sA2   = sBias + 256;           // 64
    float* sC2   = sA2 + 64;              // 64
    float* sInv  = sC2 + 64;              // 64
    int t = threadIdx.x;
    int nbase = blockIdx.x * XGN;

    for (int i = t; i < 256*64; i += 256) {
        int j = i >> 6, k = i & 63;
        sWT[k*WTSTR + j] = __uint_as_float(f2tf32(Wih[i]));
    }
    sBias[t] = bih[t] + bhh[t];
    if (t < 64) {
        float A = g2[t]*BN_INV;
        sA2[t] = A;
        sC2[t] = A*b2[t] + be2[t];
    } else if (t < 128) {
        sInv[t-64] = 1.f / g_denom2[nbase + (t-64)];
    }
    __syncthreads();

    // stage h2 once (tf32)
    for (int i = t; i < XGN*64; i += 256) {
        int nn = i >> 6, k = i & 63;
        float v = g_accum2[(nbase + nn)*64 + k] * sInv[nn];
        h2s[nn*H2STR + k] = __uint_as_float(f2tf32(eluf(v*sA2[k] + sC2[k])));
    }
    __syncthreads();

    // MMA: warp w: m-tile mt=w&3 (16 nodes), n-half nh=w>>2 (128 cols = 16 n-tiles)
    const uint32_t* h2u = (const uint32_t*)h2s;
    const uint32_t* wtu = (const uint32_t*)sWT;
    int w = t >> 5, l = t & 31;
    int g = l >> 2, c = l & 3;
    int mt = w & 3, nh = w >> 2;
    int r0 = mt*16 + g;

    float acc[16][4];
    #pragma unroll
    for (int nt = 0; nt < 16; nt++) { acc[nt][0]=0; acc[nt][1]=0; acc[nt][2]=0; acc[nt][3]=0; }

    const uint32_t* ap = h2u + r0*H2STR + c;
    #pragma unroll
    for (int ks = 0; ks < 8; ks++) {
        int kb = ks*8;
        uint32_t a[4];
        a[0] = ap[kb];
        a[1] = ap[kb + 8*H2STR];
        a[2] = ap[kb + 4];
        a[3] = ap[kb + 8*H2STR + 4];
        const uint32_t* bp0 = wtu + (kb + c)*WTSTR + nh*128 + g;
        const uint32_t* bp1 = bp0 + 4*WTSTR;
        #pragma unroll
        for (int nt = 0; nt < 16; nt++) {
            uint32_t b[2];
            b[0] = bp0[nt*8];
            b[1] = bp1[nt*8];
            mma_tf32(acc[nt], a, b);
        }
    }

    // epilogue: bias + scatter to (time, graph) rows
    int n0 = nbase + r0, n1 = n0 + 8;
    int d0 = (ntime[n0]*G_GRAPHS + batch[n0])*C1;
    int d1 = (ntime[n1]*G_GRAPHS + batch[n1])*C1;
    #pragma unroll
    for (int nt = 0; nt < 16; nt++) {
        int col = nh*128 + nt*8 + 2*c;
        float bx = sBias[col], by = sBias[col+1];
        *(float2*)&g_xgates[d0 + col] = make_float2(acc[nt][0] + bx, acc[nt][1] + by);
        *(float2*)&g_xgates[d1 + col] = make_float2(acc[nt][2] + bx, acc[nt][3] + by);
    }
}

// LSTM: 1 graph/block (512 blocks), Whh row in regs, xgates prefetch, fused FC.
__global__ void __launch_bounds__(256) k_lstm(
        const float* __restrict__ Whh, const float* __restrict__ Wfc,
        const float* __restrict__ bfc, float* __restrict__ out) {
    __shared__ float hhs[64];
    __shared__ float gates[C1];
    int t = threadIdx.x;
    int g = blockIdx.x;

    unsigned long long w2[32];
    const float4* wrow = (const float4*)(Whh + t*64);
    #pragma unroll
    for (int i = 0; i < 16; i++) {
        float4 w = wrow[i];
        w2[2*i]   = pk(w.x, w.y);
        w2[2*i+1] = pk(w.z, w.w);
    }
    if (t < 64) hhs[t] = 0.f;
    float c = 0.f;
    float xg_cur = g_xgates[g*C1 + t];
    __syncthreads();

    for (int step = 0; step < T_STEPS; step++) {
        float xg_next = 0.f;
        if (step + 1 < T_STEPS) xg_next = g_xgates[((step+1)*G_GRAPHS + g)*C1 + t];
        unsigned long long aA = 0ull, aB = 0ull;
        #pragma unroll
        for (int k2 = 0; k2 < 16; k2++) {
            ulonglong2 hv = *(const ulonglong2*)&hhs[k2*4];
            ffma2(aA, hv.x, w2[2*k2]);
            ffma2(aB, hv.y, w2[2*k2+1]);
        }
        float2 a = unpk(aA), b = unpk(aB);
        gates[t] = xg_cur + a.x + a.y + b.x + b.y;
        __syncthreads();
        if (t < 64) {
            float ig = gates[t],       fg = gates[64 + t];
            float gg = gates[128 + t], og = gates[192 + t];
            c = sigf(fg)*c + sigf(ig)*tanhf(gg);
            hhs[t] = sigf(og)*tanhf(c);
        }
        __syncthreads();
        xg_cur = xg_next;
    }
    if (t < OUT_DIM) {
        float acc = bfc[t];
        #pragma unroll 8
        for (int k = 0; k < 64; k++) acc += hhs[k] * Wfc[k*OUT_DIM + t];
        out[g*OUT_DIM + t] = acc;
    }
}

// ---------------- launch ----------------
static const int SMEM_P2 = (256*W2STR + 2048 + P2N*H1STR + 64 + 64 + 128 + 128) * 4; // 110592
static const int SMEM_XG = (64*WTSTR + XGN*H2STR + 256 + 64 + 64 + 64) * 4;          // 86784

extern "C" void kernel_launch(void* const* d_in, const int* in_sizes, int n_in,
                              void* d_out, int out_size) {
    const float* x    = (const float*)d_in[0];
    const int*   ei   = (const int*)  d_in[1];
    const int*   batch= (const int*)  d_in[2];
    const int*   ntime= (const int*)  d_in[3];
    const float* W1   = (const float*)d_in[4];
    const float* as1  = (const float*)d_in[5];
    const float* ad1  = (const float*)d_in[6];
    const float* b1   = (const float*)d_in[7];
    const float* g1   = (const float*)d_in[8];
    const float* be1  = (const float*)d_in[9];
    const float* W2   = (const float*)d_in[10];
    const float* as2  = (const float*)d_in[11];
    const float* ad2  = (const float*)d_in[12];
    const float* b2   = (const float*)d_in[13];
    const float* g2   = (const float*)d_in[14];
    const float* be2  = (const float*)d_in[15];
    const float* Wih  = (const float*)d_in[16];
    const float* Whh  = (const float*)d_in[17];
    const float* bih  = (const float*)d_in[18];
    const float* bhh  = (const float*)d_in[19];
    const float* Wfc  = (const float*)d_in[20];
    const float* bfc  = (const float*)d_in[21];
    float* out = (float*)d_out;

    cudaFuncSetAttribute(k_proj2f,  cudaFuncAttributeMaxDynamicSharedMemorySize, SMEM_P2);
    cudaFuncSetAttribute(k_xgates2, cudaFuncAttributeMaxDynamicSharedMemorySize, SMEM_XG);

    void *p_xagg, *p_acc2, *p_den2;
    cudaGetSymbolAddress(&p_xagg, g_xagg);
    cudaGetSymbolAddress(&p_acc2, g_accum2);
    cudaGetSymbolAddress(&p_den2, g_denom2);
    cudaMemsetAsync(p_xagg, 0, sizeof(float)*N_NODES*32);
    cudaMemsetAsync(p_acc2, 0, sizeof(float)*N_NODES*HID);
    cudaMemsetAsync(p_den2, 0, sizeof(float)*N_NODES);

    k_pre1   <<<1, 64>>>(W1, as1, ad1);
    k_att1   <<<(N_NODES + 255)/256, 256>>>(x);
    k_esum1  <<<(ETOT + 255)/256, 256>>>(ei);
    k_proj2f <<<N_NODES/P2N, 256, SMEM_P2>>>(W1, b1, g1, be1, W2, as2, ad2);
    k_esum2  <<<(ETOT*8 + 255)/256, 256>>>(ei);
    k_xgates2<<<N_NODES/XGN, 256, SMEM_XG>>>(Wih, bih, bhh, b2, g2, be2, batch, ntime);
    k_lstm   <<<G_GRAPHS, 256>>>(Whh, Wfc, bfc, out);
}

// round 12
// speedup vs baseline: 1.4272x; 1.0874x over previous
#include <cuda_runtime.h>
#include <math.h>
#include <stdint.h>

#define N_NODES 25600
#define N_EDGES 204800
#define ETOT    (N_EDGES + N_NODES)   // 230400
#define IN_CH   6
#define HID     64
#define HEADS   4
#define C1      (HEADS*HID)           // 256
#define G_GRAPHS 512
#define T_STEPS  50
#define OUT_DIM  30
#define NEG_SLOPE 0.2f
#define BN_INV 0.9999950000374996f    // 1/sqrt(1+1e-5)

// ---------------- scratch ----------------
__device__ float g_wsrc[24];
__device__ float g_wdst[24];
__device__ __align__(16) float g_x8[N_NODES*8];
__device__ __align__(16) float g_asrc1[N_NODES*4];
__device__ __align__(16) float g_adst1[N_NODES*4];
__device__ __align__(16) float g_xagg[N_NODES*32];    // 4 heads x [x0..x5, denom, 0]
__device__ __align__(16) float g_hproj2[N_NODES*HID];
__device__ float g_asrc2[N_NODES];
__device__ float g_adst2[N_NODES];
__device__ float g_denom2[N_NODES];
__device__ __align__(16) float g_accum2[N_NODES*HID];
__device__ __align__(16) float g_xgates[N_NODES*C1];  // (t, g, 256)
__device__ __align__(16) uint32_t g_W2t[256*64];      // tf32 bits, [k][j]
__device__ __align__(16) uint32_t g_WihT[64*256];     // tf32 bits, [k][j] (Wih^T)

// ---------------- helpers ----------------
__device__ __forceinline__ float lrelu(float v) { return v > 0.f ? v : NEG_SLOPE*v; }
__device__ __forceinline__ float eluf(float v)  { return v > 0.f ? v : (__expf(v) - 1.f); }
__device__ __forceinline__ float sigf(float v)  { return 1.f/(1.f+expf(-v)); }

__device__ __forceinline__ void redAdd4(float* addr, float a, float b, float c, float d) {
    asm volatile("red.global.add.v4.f32 [%0], {%1,%2,%3,%4};"
                 :: "l"(addr), "f"(a), "f"(b), "f"(c), "f"(d) : "memory");
}
__device__ __forceinline__ void ffma2(unsigned long long& d, unsigned long long a,
                                      unsigned long long b) {
    asm("fma.rn.f32x2 %0, %1, %2, %0;" : "+l"(d) : "l"(a), "l"(b));
}
__device__ __forceinline__ unsigned long long pk(float a, float b) {
    unsigned long long r;
    asm("mov.b64 %0, {%1, %2};" : "=l"(r) : "f"(a), "f"(b));
    return r;
}
__device__ __forceinline__ float2 unpk(unsigned long long v) {
    float2 r;
    asm("mov.b64 {%0, %1}, %2;" : "=f"(r.x), "=f"(r.y) : "l"(v));
    return r;
}
__device__ __forceinline__ uint32_t f2tf32(float v) {
    uint32_t r;
    asm("cvt.rna.tf32.f32 %0, %1;" : "=r"(r) : "f"(v));
    return r;
}
// m16n8k8 tf32 MMA, fp32 accumulate (in-place)
__device__ __forceinline__ void mma_tf32(float* d, const uint32_t* a, const uint32_t* b) {
    asm("mma.sync.aligned.m16n8k8.row.col.f32.tf32.tf32.f32 "
        "{%0,%1,%2,%3},{%4,%5,%6,%7},{%8,%9},{%0,%1,%2,%3};"
        : "+f"(d[0]), "+f"(d[1]), "+f"(d[2]), "+f"(d[3])
        : "r"(a[0]), "r"(a[1]), "r"(a[2]), "r"(a[3]), "r"(b[0]), "r"(b[1]));
}

// ---------------- kernels ----------------
__global__ void k_pre1(const float* __restrict__ W1, const float* __restrict__ as1,
                       const float* __restrict__ ad1) {
    int t = threadIdx.x;
    if (t < 24) {
        int k = t >> 2, h = t & 3;
        float s = 0.f;
        for (int c = 0; c < 64; c++) s += W1[k*C1 + h*64 + c] * as1[h*64 + c];
        g_wsrc[t] = s;
    } else if (t >= 32 && t < 56) {
        int i = t - 32, k = i >> 2, h = i & 3;
        float s = 0.f;
        for (int c = 0; c < 64; c++) s += W1[k*C1 + h*64 + c] * ad1[h*64 + c];
        g_wdst[i] = s;
    }
}

// one-off weight conversion to tf32 (global)
__global__ void k_cvtW(const float* __restrict__ W2, const float* __restrict__ Wih) {
    int i = blockIdx.x*blockDim.x + threadIdx.x;
    if (i < 16384) {
        g_W2t[i] = f2tf32(W2[i]);                  // layout already [k][64]
        int j = i >> 6, k = i & 63;                // Wih is [j][k]
        g_WihT[k*256 + j] = f2tf32(Wih[i]);        // -> [k][256]
    }
}

__global__ void k_att1(const float* __restrict__ x) {
    int n = blockIdx.x*blockDim.x + threadIdx.x;
    if (n >= N_NODES) return;
    float2 xa = *(const float2*)&x[n*6];
    float2 xb = *(const float2*)&x[n*6 + 2];
    float2 xc = *(const float2*)&x[n*6 + 4];
    float xv[6] = {xa.x, xa.y, xb.x, xb.y, xc.x, xc.y};
    float s[4] = {0,0,0,0}, d[4] = {0,0,0,0};
    #pragma unroll
    for (int k = 0; k < 6; k++) {
        #pragma unroll
        for (int h = 0; h < 4; h++) {
            s[h] += xv[k]*g_wsrc[k*4+h];
            d[h] += xv[k]*g_wdst[k*4+h];
        }
    }
    *(float4*)&g_asrc1[n*4] = make_float4(s[0],s[1],s[2],s[3]);
    *(float4*)&g_adst1[n*4] = make_float4(d[0],d[1],d[2],d[3]);
    *(float4*)&g_x8[n*8]     = make_float4(xv[0],xv[1],xv[2],xv[3]);
    *(float4*)&g_x8[n*8 + 4] = make_float4(xv[4],xv[5],0.f,0.f);
}

__global__ void k_esum1(const int* __restrict__ ei) {
    int e = blockIdx.x*blockDim.x + threadIdx.x;
    if (e >= ETOT) return;
    int s, d;
    if (e < N_EDGES) { s = ei[e]; d = ei[N_EDGES + e]; } else { s = d = e - N_EDGES; }
    float4 as = *(const float4*)&g_asrc1[s*4];
    float4 ad = *(const float4*)&g_adst1[d*4];
    float ex[4];
    ex[0] = expf(lrelu(as.x + ad.x));
    ex[1] = expf(lrelu(as.y + ad.y));
    ex[2] = expf(lrelu(as.z + ad.z));
    ex[3] = expf(lrelu(as.w + ad.w));
    float4 xa = *(const float4*)&g_x8[s*8];
    float4 xb = *(const float4*)&g_x8[s*8 + 4];
    float* base = &g_xagg[d*32];
    #pragma unroll
    for (int h = 0; h < 4; h++) {
        float w = ex[h];
        redAdd4(base + h*8,     w*xa.x, w*xa.y, w*xa.z, w*xa.w);
        redAdd4(base + h*8 + 4, w*xb.x, w*xb.y, w,      0.f);
    }
}

// fused GAT2 projection via tf32 MMA. h1 staged in smem; B fragments from L1 (global tf32).
#define P2N 32
#define H1STR 260          // (4r + k) % 32 -> conflict-free A frags
__global__ void __launch_bounds__(256, 4) k_proj2f(
        const float* __restrict__ W1, const float* __restrict__ b1,
        const float* __restrict__ g1, const float* __restrict__ be1,
        const float* __restrict__ as2, const float* __restrict__ ad2) {
    extern __shared__ float sm[];
    float* sW1p = sm;                      // [256][8]: {w0..w5, A, C} f32 = 2048
    float* h1s  = sW1p + 2048;             // [32][260] tf32 bits
    float* sAs  = h1s + P2N*H1STR;         // 64
    float* sAd  = sAs + 64;                // 64
    float* sS   = sAd + 64;                // 128
    float* sD   = sS + 128;                // 128
    int t = threadIdx.x;
    int nbase = blockIdx.x * P2N;

    for (int i = t; i < 2048; i += 256) {
        int c = i >> 3, r = i & 7;
        float v;
        if (r < 6)       v = W1[r*C1 + c];
        else if (r == 6) v = g1[c]*BN_INV;
        else { float A = g1[c]*BN_INV; v = A*b1[c] + be1[c]; }
        sW1p[i] = v;
    }
    if (t < 64)            sAs[t] = as2[t];
    else if (t < 128)      sAd[t-64] = ad2[t-64];
    __syncthreads();

    // phase 1: h1 (tf32) — thread (nl, q) computes cols [q*32, q*32+32) of node nl
    {
        int nl = t & 31, q = t >> 5;
        int n  = nbase + nl;
        float xr[24];
        #pragma unroll
        for (int h = 0; h < 4; h++) {
            float4 v0 = *(const float4*)&g_xagg[n*32 + h*8];
            float4 v1 = *(const float4*)&g_xagg[n*32 + h*8 + 4];
            float inv = 1.f / v1.z;
            xr[h*6+0] = v0.x*inv; xr[h*6+1] = v0.y*inv; xr[h*6+2] = v0.z*inv;
            xr[h*6+3] = v0.w*inv; xr[h*6+4] = v1.x*inv; xr[h*6+5] = v1.y*inv;
        }
        #pragma unroll 4
        for (int c2 = 0; c2 < 32; c2++) {
            int c = q*32 + c2;
            float4 wa = *(const float4*)&sW1p[c*8];
            float4 wb = *(const float4*)&sW1p[c*8 + 4];
            int h = c >> 6;
            float dot = xr[h*6+0]*wa.x + xr[h*6+1]*wa.y + xr[h*6+2]*wa.z
                      + xr[h*6+3]*wa.w + xr[h*6+4]*wb.x + xr[h*6+5]*wb.y;
            h1s[nl*H1STR + c] = __uint_as_float(f2tf32(eluf(dot*wb.z + wb.w)));
        }
    }
    __syncthreads();

    // phase 2: MMA. warp w: m-tile mt=w&1 (16 nodes), n-quarter nq=w>>1 (16 cols)
    const uint32_t* h1u = (const uint32_t*)h1s;
    int w = t >> 5, l = t & 31;
    int g = l >> 2, c = l & 3;
    int mt = w & 1, nq = w >> 1;
    int r0 = mt*16 + g;

    float acc[2][4];
    #pragma unroll
    for (int nt = 0; nt < 2; nt++) { acc[nt][0]=0; acc[nt][1]=0; acc[nt][2]=0; acc[nt][3]=0; }

    const uint32_t* ap = h1u + r0*H1STR + c;
    #pragma unroll 4
    for (int ks = 0; ks < 32; ks++) {
        int kb = ks*8;
        uint32_t a[4];
        a[0] = ap[kb];
        a[1] = ap[kb + 8*H1STR];
        a[2] = ap[kb + 4];
        a[3] = ap[kb + 8*H1STR + 4];
        #pragma unroll
        for (int nt = 0; nt < 2; nt++) {
            int nb = nq*16 + nt*8;
            uint32_t b[2];
            b[0] = __ldg(&g_W2t[(kb + c)*64 + nb + g]);
            b[1] = __ldg(&g_W2t[(kb + c + 4)*64 + nb + g]);
            mma_tf32(acc[nt], a, b);
        }
    }

    // epilogue: store hproj2 + att2 partial dots
    float s0 = 0.f, d0 = 0.f, s1 = 0.f, d1 = 0.f;
    int n0 = nbase + r0, n1 = n0 + 8;
    #pragma unroll
    for (int nt = 0; nt < 2; nt++) {
        int col = nq*16 + nt*8 + 2*c;
        *(float2*)&g_hproj2[n0*64 + col] = make_float2(acc[nt][0], acc[nt][1]);
        *(float2*)&g_hproj2[n1*64 + col] = make_float2(acc[nt][2], acc[nt][3]);
        s0 += acc[nt][0]*sAs[col] + acc[nt][1]*sAs[col+1];
        d0 += acc[nt][0]*sAd[col] + acc[nt][1]*sAd[col+1];
        s1 += acc[nt][2]*sAs[col] + acc[nt][3]*sAs[col+1];
        d1 += acc[nt][2]*sAd[col] + acc[nt][3]*sAd[col+1];
    }
    #pragma unroll
    for (int m = 1; m < 4; m <<= 1) {
        s0 += __shfl_xor_sync(~0u, s0, m);
        d0 += __shfl_xor_sync(~0u, d0, m);
        s1 += __shfl_xor_sync(~0u, s1, m);
        d1 += __shfl_xor_sync(~0u, d1, m);
    }
    if (c == 0) {
        sS[r0*4 + nq] = s0; sD[r0*4 + nq] = d0;
        sS[(r0+8)*4 + nq] = s1; sD[(r0+8)*4 + nq] = d1;
    }
    __syncthreads();
    if (t < P2N) {
        float ss = sS[t*4] + sS[t*4+1] + sS[t*4+2] + sS[t*4+3];
        float dd = sD[t*4] + sD[t*4+1] + sD[t*4+2] + sD[t*4+3];
        g_asrc2[nbase + t] = ss;
        g_adst2[nbase + t] = dd;
    }
}

// 8 threads/edge: denom += ex; accum2[dst] += ex*hproj2[src]
__global__ void k_esum2(const int* __restrict__ ei) {
    int gt = blockIdx.x*blockDim.x + threadIdx.x;
    int e = gt >> 3, q = gt & 7;
    if (e >= ETOT) return;
    int s, d;
    if (e < N_EDGES) { s = ei[e]; d = ei[N_EDGES + e]; } else { s = d = e - N_EDGES; }
    float ex = expf(lrelu(g_asrc2[s] + g_adst2[d]));
    if (q == 0) atomicAdd(&g_denom2[d], ex);
    int c = q*8;
    float4 v1 = *(const float4*)&g_hproj2[s*64 + c];
    float4 v2 = *(const float4*)&g_hproj2[s*64 + c + 4];
    redAdd4(&g_accum2[d*64 + c],     v1.x*ex, v1.y*ex, v1.z*ex, v1.w*ex);
    redAdd4(&g_accum2[d*64 + c + 4], v2.x*ex, v2.y*ex, v2.z*ex, v2.w*ex);
}

// fused: h2 staged once as tf32; xgates = h2@Wih^T + biases via tf32 MMA (scattered rows).
// 32 nodes/block; warp = (m-tile mt=w&1, 64-col group nh=w>>1); B frags from L1.
#define XGN 32
#define H2STR 68           // (4r + k) % 32 -> conflict-free A frags
__global__ void __launch_bounds__(256, 4) k_xgates2(
        const float* __restrict__ bih, const float* __restrict__ bhh,
        const float* __restrict__ b2, const float* __restrict__ g2,
        const float* __restrict__ be2,
        const int* __restrict__ batch, const int* __restrict__ ntime) {
    extern __shared__ float sm[];
    float* h2s   = sm;                    // [32][68] tf32 bits
    float* sBias = h2s + XGN*H2STR;       // 256
    float* sA2   = sBias + 256;           // 64
    float* sC2   = sA2 + 64;              // 64
    float* sInv  = sC2 + 64;              // 32
    int t = threadIdx.x;
    int nbase = blockIdx.x * XGN;

    sBias[t] = bih[t] + bhh[t];
    if (t < 64) {
        float A = g2[t]*BN_INV;
        sA2[t] = A;
        sC2[t] = A*b2[t] + be2[t];
    } else if (t >= 128 && t < 160) {
        sInv[t-128] = 1.f / g_denom2[nbase + (t-128)];
    }
    __syncthreads();

    // stage h2 once (tf32)
    for (int i = t; i < XGN*64; i += 256) {
        int nn = i >> 6, k = i & 63;
        float v = g_accum2[(nbase + nn)*64 + k] * sInv[nn];
        h2s[nn*H2STR + k] = __uint_as_float(f2tf32(eluf(v*sA2[k] + sC2[k])));
    }
    __syncthreads();

    const uint32_t* h2u = (const uint32_t*)h2s;
    int w = t >> 5, l = t & 31;
    int g = l >> 2, c = l & 3;
    int mt = w & 1, nh = w >> 1;   // nh in 0..3: 64-col group
    int r0 = mt*16 + g;

    float acc[8][4];
    #pragma unroll
    for (int nt = 0; nt < 8; nt++) { acc[nt][0]=0; acc[nt][1]=0; acc[nt][2]=0; acc[nt][3]=0; }

    const uint32_t* ap = h2u + r0*H2STR + c;
    #pragma unroll
    for (int ks = 0; ks < 8; ks++) {
        int kb = ks*8;
        uint32_t a[4];
        a[0] = ap[kb];
        a[1] = ap[kb + 8*H2STR];
        a[2] = ap[kb + 4];
        a[3] = ap[kb + 8*H2STR + 4];
        const uint32_t* bp0 = &g_WihT[(kb + c)*256 + nh*64 + g];
        const uint32_t* bp1 = bp0 + 4*256;
        #pragma unroll
        for (int nt = 0; nt < 8; nt++) {
            uint32_t b[2];
            b[0] = __ldg(&bp0[nt*8]);
            b[1] = __ldg(&bp1[nt*8]);
            mma_tf32(acc[nt], a, b);
        }
    }

    // epilogue: bias + scatter to (time, graph) rows
    int n0 = nbase + r0, n1 = n0 + 8;
    int d0 = (ntime[n0]*G_GRAPHS + batch[n0])*C1;
    int d1 = (ntime[n1]*G_GRAPHS + batch[n1])*C1;
    #pragma unroll
    for (int nt = 0; nt < 8; nt++) {
        int col = nh*64 + nt*8 + 2*c;
        float bx = sBias[col], by = sBias[col+1];
        *(float2*)&g_xgates[d0 + col] = make_float2(acc[nt][0] + bx, acc[nt][1] + by);
        *(float2*)&g_xgates[d1 + col] = make_float2(acc[nt][2] + bx, acc[nt][3] + by);
    }
}

// LSTM: 1 graph/block (512 blocks), Whh row in regs, xgates prefetch, fused FC.
__global__ void __launch_bounds__(256) k_lstm(
        const float* __restrict__ Whh, const float* __restrict__ Wfc,
        const float* __restrict__ bfc, float* __restrict__ out) {
    __shared__ float hhs[64];
    __shared__ float gates[C1];
    int t = threadIdx.x;
    int g = blockIdx.x;

    unsigned long long w2[32];
    const float4* wrow = (const float4*)(Whh + t*64);
    #pragma unroll
    for (int i = 0; i < 16; i++) {
        float4 w = wrow[i];
        w2[2*i]   = pk(w.x, w.y);
        w2[2*i+1] = pk(w.z, w.w);
    }
    if (t < 64) hhs[t] = 0.f;
    float c = 0.f;
    float xg_cur = g_xgates[g*C1 + t];
    __syncthreads();

    for (int step = 0; step < T_STEPS; step++) {
        float xg_next = 0.f;
        if (step + 1 < T_STEPS) xg_next = g_xgates[((step+1)*G_GRAPHS + g)*C1 + t];
        unsigned long long aA = 0ull, aB = 0ull;
        #pragma unroll
        for (int k2 = 0; k2 < 16; k2++) {
            ulonglong2 hv = *(const ulonglong2*)&hhs[k2*4];
            ffma2(aA, hv.x, w2[2*k2]);
            ffma2(aB, hv.y, w2[2*k2+1]);
        }
        float2 a = unpk(aA), b = unpk(aB);
        gates[t] = xg_cur + a.x + a.y + b.x + b.y;
        __syncthreads();
        if (t < 64) {
            float ig = gates[t],       fg = gates[64 + t];
            float gg = gates[128 + t], og = gates[192 + t];
            c = sigf(fg)*c + sigf(ig)*tanhf(gg);
            hhs[t] = sigf(og)*tanhf(c);
        }
        __syncthreads();
        xg_cur = xg_next;
    }
    if (t < OUT_DIM) {
        float acc = bfc[t];
        #pragma unroll 8
        for (int k = 0; k < 64; k++) acc += hhs[k] * Wfc[k*OUT_DIM + t];
        out[g*OUT_DIM + t] = acc;
    }
}

// ---------------- launch ----------------
static const int SMEM_P2 = (2048 + P2N*H1STR + 64 + 64 + 128 + 128) * 4;   // 43008 B
static const int SMEM_XG = (XGN*H2STR + 256 + 64 + 64 + 32) * 4;           // 10368 B

extern "C" void kernel_launch(void* const* d_in, const int* in_sizes, int n_in,
                              void* d_out, int out_size) {
    const float* x    = (const float*)d_in[0];
    const int*   ei   = (const int*)  d_in[1];
    const int*   batch= (const int*)  d_in[2];
    const int*   ntime= (const int*)  d_in[3];
    const float* W1   = (const float*)d_in[4];
    const float* as1  = (const float*)d_in[5];
    const float* ad1  = (const float*)d_in[6];
    const float* b1   = (const float*)d_in[7];
    const float* g1   = (const float*)d_in[8];
    const float* be1  = (const float*)d_in[9];
    const float* W2   = (const float*)d_in[10];
    const float* as2  = (const float*)d_in[11];
    const float* ad2  = (const float*)d_in[12];
    const float* b2   = (const float*)d_in[13];
    const float* g2   = (const float*)d_in[14];
    const float* be2  = (const float*)d_in[15];
    const float* Wih  = (const float*)d_in[16];
    const float* Whh  = (const float*)d_in[17];
    const float* bih  = (const float*)d_in[18];
    const float* bhh  = (const float*)d_in[19];
    const float* Wfc  = (const float*)d_in[20];
    const float* bfc  = (const float*)d_in[21];
    float* out = (float*)d_out;

    cudaFuncSetAttribute(k_proj2f,  cudaFuncAttributeMaxDynamicSharedMemorySize, SMEM_P2);
    cudaFuncSetAttribute(k_xgates2, cudaFuncAttributeMaxDynamicSharedMemorySize, SMEM_XG);

    void *p_xagg, *p_acc2, *p_den2;
    cudaGetSymbolAddress(&p_xagg, g_xagg);
    cudaGetSymbolAddress(&p_acc2, g_accum2);
    cudaGetSymbolAddress(&p_den2, g_denom2);
    cudaMemsetAsync(p_xagg, 0, sizeof(float)*N_NODES*32);
    cudaMemsetAsync(p_acc2, 0, sizeof(float)*N_NODES*HID);
    cudaMemsetAsync(p_den2, 0, sizeof(float)*N_NODES);

    k_pre1   <<<1, 64>>>(W1, as1, ad1);
    k_cvtW   <<<64, 256>>>(W2, Wih);
    k_att1   <<<(N_NODES + 255)/256, 256>>>(x);
    k_esum1  <<<(ETOT + 255)/256, 256>>>(ei);
    k_proj2f <<<N_NODES/P2N, 256, SMEM_P2>>>(W1, b1, g1, be1, as2, ad2);
    k_esum2  <<<(ETOT*8 + 255)/256, 256>>>(ei);
    k_xgates2<<<N_NODES/XGN, 256, SMEM_XG>>>(bih, bhh, b2, g2, be2, batch, ntime);
    k_lstm   <<<G_GRAPHS, 256>>>(Whh, Wfc, bfc, out);
}

// round 13
// speedup vs baseline: 1.4449x; 1.0124x over previous
#include <cuda_runtime.h>
#include <math.h>
#include <stdint.h>

#define N_NODES 25600
#define N_EDGES 204800
#define ETOT    (N_EDGES + N_NODES)   // 230400
#define EHALF   (ETOT/2)              // 115200
#define IN_CH   6
#define HID     64
#define HEADS   4
#define C1      (HEADS*HID)           // 256
#define G_GRAPHS 512
#define T_STEPS  50
#define OUT_DIM  30
#define NEG_SLOPE 0.2f
#define BN_INV 0.9999950000374996f    // 1/sqrt(1+1e-5)

// ---------------- scratch ----------------
__device__ float g_wsrc[24];
__device__ float g_wdst[24];
__device__ __align__(16) float g_x8[N_NODES*8];
__device__ __align__(16) float g_asrc1[N_NODES*4];
__device__ __align__(16) float g_adst1[N_NODES*4];
__device__ __align__(16) float g_xagg[N_NODES*32];    // 4 heads x [x0..x5, denom, 0]
__device__ __align__(16) float g_hproj2[N_NODES*HID];
__device__ float g_asrc2[N_NODES];
__device__ float g_adst2[N_NODES];
__device__ float g_denom2[N_NODES];
__device__ __align__(16) float g_accum2[N_NODES*HID];
__device__ __align__(16) float g_xgates[N_NODES*C1];  // (t, g, 256)
__device__ __align__(16) uint32_t g_W2t[256*64];      // tf32 bits, [k][j]
__device__ __align__(16) uint32_t g_WihT[64*256];     // tf32 bits, [k][j] (Wih^T)

// ---------------- helpers ----------------
__device__ __forceinline__ float lrelu(float v) { return v > 0.f ? v : NEG_SLOPE*v; }
__device__ __forceinline__ float eluf(float v)  { return v > 0.f ? v : (__expf(v) - 1.f); }
__device__ __forceinline__ float sigf(float v)  { return 1.f/(1.f+expf(-v)); }

__device__ __forceinline__ void redAdd4(float* addr, float a, float b, float c, float d) {
    asm volatile("red.global.add.v4.f32 [%0], {%1,%2,%3,%4};"
                 :: "l"(addr), "f"(a), "f"(b), "f"(c), "f"(d) : "memory");
}
__device__ __forceinline__ void ffma2(unsigned long long& d, unsigned long long a,
                                      unsigned long long b) {
    asm("fma.rn.f32x2 %0, %1, %2, %0;" : "+l"(d) : "l"(a), "l"(b));
}
__device__ __forceinline__ unsigned long long pk(float a, float b) {
    unsigned long long r;
    asm("mov.b64 %0, {%1, %2};" : "=l"(r) : "f"(a), "f"(b));
    return r;
}
__device__ __forceinline__ float2 unpk(unsigned long long v) {
    float2 r;
    asm("mov.b64 {%0, %1}, %2;" : "=f"(r.x), "=f"(r.y) : "l"(v));
    return r;
}
__device__ __forceinline__ uint32_t f2tf32(float v) {
    uint32_t r;
    asm("cvt.rna.tf32.f32 %0, %1;" : "=r"(r) : "f"(v));
    return r;
}
// m16n8k8 tf32 MMA, fp32 accumulate (in-place)
__device__ __forceinline__ void mma_tf32(float* d, const uint32_t* a, const uint32_t* b) {
    asm("mma.sync.aligned.m16n8k8.row.col.f32.tf32.tf32.f32 "
        "{%0,%1,%2,%3},{%4,%5,%6,%7},{%8,%9},{%0,%1,%2,%3};"
        : "+f"(d[0]), "+f"(d[1]), "+f"(d[2]), "+f"(d[3])
        : "r"(a[0]), "r"(a[1]), "r"(a[2]), "r"(a[3]), "r"(b[0]), "r"(b[1]));
}

// ---------------- kernels ----------------
// merged prep: tf32 weight conversion (all blocks) + attention row-vectors (block 0)
__global__ void k_prep(const float* __restrict__ W1, const float* __restrict__ as1,
                       const float* __restrict__ ad1,
                       const float* __restrict__ W2, const float* __restrict__ Wih) {
    int i = blockIdx.x*blockDim.x + threadIdx.x;
    if (i < 16384) {
        g_W2t[i] = f2tf32(W2[i]);                  // layout already [k][64]
        int j = i >> 6, k = i & 63;                // Wih is [j][k]
        g_WihT[k*256 + j] = f2tf32(Wih[i]);        // -> [k][256]
    }
    if (blockIdx.x == 0) {
        int t = threadIdx.x;
        if (t < 24) {
            int k = t >> 2, h = t & 3;
            float s = 0.f;
            for (int c = 0; c < 64; c++) s += W1[k*C1 + h*64 + c] * as1[h*64 + c];
            g_wsrc[t] = s;
        } else if (t >= 32 && t < 56) {
            int q = t - 32, k = q >> 2, h = q & 3;
            float s = 0.f;
            for (int c = 0; c < 64; c++) s += W1[k*C1 + h*64 + c] * ad1[h*64 + c];
            g_wdst[q] = s;
        }
    }
}

__global__ void k_att1(const float* __restrict__ x) {
    int n = blockIdx.x*blockDim.x + threadIdx.x;
    if (n >= N_NODES) return;
    float2 xa = *(const float2*)&x[n*6];
    float2 xb = *(const float2*)&x[n*6 + 2];
    float2 xc = *(const float2*)&x[n*6 + 4];
    float xv[6] = {xa.x, xa.y, xb.x, xb.y, xc.x, xc.y};
    float s[4] = {0,0,0,0}, d[4] = {0,0,0,0};
    #pragma unroll
    for (int k = 0; k < 6; k++) {
        #pragma unroll
        for (int h = 0; h < 4; h++) {
            s[h] += xv[k]*g_wsrc[k*4+h];
            d[h] += xv[k]*g_wdst[k*4+h];
        }
    }
    *(float4*)&g_asrc1[n*4] = make_float4(s[0],s[1],s[2],s[3]);
    *(float4*)&g_adst1[n*4] = make_float4(d[0],d[1],d[2],d[3]);
    *(float4*)&g_x8[n*8]     = make_float4(xv[0],xv[1],xv[2],xv[3]);
    *(float4*)&g_x8[n*8 + 4] = make_float4(xv[4],xv[5],0.f,0.f);
}

// 2 edges per thread for doubled memory-level parallelism
__global__ void k_esum1(const int* __restrict__ ei) {
    int e0 = blockIdx.x*blockDim.x + threadIdx.x;
    if (e0 >= EHALF) return;
    #pragma unroll
    for (int rep = 0; rep < 2; rep++) {
        int e = e0 + rep*EHALF;
        int s, d;
        if (e < N_EDGES) { s = ei[e]; d = ei[N_EDGES + e]; } else { s = d = e - N_EDGES; }
        float4 as = *(const float4*)&g_asrc1[s*4];
        float4 ad = *(const float4*)&g_adst1[d*4];
        float ex[4];
        ex[0] = expf(lrelu(as.x + ad.x));
        ex[1] = expf(lrelu(as.y + ad.y));
        ex[2] = expf(lrelu(as.z + ad.z));
        ex[3] = expf(lrelu(as.w + ad.w));
        float4 xa = *(const float4*)&g_x8[s*8];
        float4 xb = *(const float4*)&g_x8[s*8 + 4];
        float* base = &g_xagg[d*32];
        #pragma unroll
        for (int h = 0; h < 4; h++) {
            float w = ex[h];
            redAdd4(base + h*8,     w*xa.x, w*xa.y, w*xa.z, w*xa.w);
            redAdd4(base + h*8 + 4, w*xb.x, w*xb.y, w,      0.f);
        }
    }
}

// fused GAT2 projection via tf32 MMA. h1 staged in smem; B fragments from L1 (global tf32).
#define P2N 32
#define H1STR 260          // (4r + k) % 32 -> conflict-free A frags
__global__ void __launch_bounds__(256, 4) k_proj2f(
        const float* __restrict__ W1, const float* __restrict__ b1,
        const float* __restrict__ g1, const float* __restrict__ be1,
        const float* __restrict__ as2, const float* __restrict__ ad2) {
    extern __shared__ float sm[];
    float* sW1p = sm;                      // [256][8]: {w0..w5, A, C} f32 = 2048
    float* h1s  = sW1p + 2048;             // [32][260] tf32 bits
    float* sAs  = h1s + P2N*H1STR;         // 64
    float* sAd  = sAs + 64;                // 64
    float* sS   = sAd + 64;                // 128
    float* sD   = sS + 128;                // 128
    int t = threadIdx.x;
    int nbase = blockIdx.x * P2N;

    for (int i = t; i < 2048; i += 256) {
        int c = i >> 3, r = i & 7;
        float v;
        if (r < 6)       v = W1[r*C1 + c];
        else if (r == 6) v = g1[c]*BN_INV;
        else { float A = g1[c]*BN_INV; v = A*b1[c] + be1[c]; }
        sW1p[i] = v;
    }
    if (t < 64)            sAs[t] = as2[t];
    else if (t < 128)      sAd[t-64] = ad2[t-64];
    __syncthreads();

    // phase 1: h1 (tf32) — thread (nl, q) computes cols [q*32, q*32+32) of node nl
    {
        int nl = t & 31, q = t >> 5;
        int n  = nbase + nl;
        float xr[24];
        #pragma unroll
        for (int h = 0; h < 4; h++) {
            float4 v0 = *(const float4*)&g_xagg[n*32 + h*8];
            float4 v1 = *(const float4*)&g_xagg[n*32 + h*8 + 4];
            float inv = 1.f / v1.z;
            xr[h*6+0] = v0.x*inv; xr[h*6+1] = v0.y*inv; xr[h*6+2] = v0.z*inv;
            xr[h*6+3] = v0.w*inv; xr[h*6+4] = v1.x*inv; xr[h*6+5] = v1.y*inv;
        }
        #pragma unroll 4
        for (int c2 = 0; c2 < 32; c2++) {
            int c = q*32 + c2;
            float4 wa = *(const float4*)&sW1p[c*8];
            float4 wb = *(const float4*)&sW1p[c*8 + 4];
            int h = c >> 6;
            float dot = xr[h*6+0]*wa.x + xr[h*6+1]*wa.y + xr[h*6+2]*wa.z
                      + xr[h*6+3]*wa.w + xr[h*6+4]*wb.x + xr[h*6+5]*wb.y;
            h1s[nl*H1STR + c] = __uint_as_float(f2tf32(eluf(dot*wb.z + wb.w)));
        }
    }
    __syncthreads();

    // phase 2: MMA. warp w: m-tile mt=w&1 (16 nodes), n-quarter nq=w>>1 (16 cols)
    const uint32_t* h1u = (const uint32_t*)h1s;
    int w = t >> 5, l = t & 31;
    int g = l >> 2, c = l & 3;
    int mt = w & 1, nq = w >> 1;
    int r0 = mt*16 + g;

    float acc[2][4];
    #pragma unroll
    for (int nt = 0; nt < 2; nt++) { acc[nt][0]=0; acc[nt][1]=0; acc[nt][2]=0; acc[nt][3]=0; }

    const uint32_t* ap = h1u + r0*H1STR + c;
    #pragma unroll 8
    for (int ks = 0; ks < 32; ks++) {
        int kb = ks*8;
        uint32_t a[4];
        a[0] = ap[kb];
        a[1] = ap[kb + 8*H1STR];
        a[2] = ap[kb + 4];
        a[3] = ap[kb + 8*H1STR + 4];
        #pragma unroll
        for (int nt = 0; nt < 2; nt++) {
            int nb = nq*16 + nt*8;
            uint32_t b[2];
            b[0] = __ldg(&g_W2t[(kb + c)*64 + nb + g]);
            b[1] = __ldg(&g_W2t[(kb + c + 4)*64 + nb + g]);
            mma_tf32(acc[nt], a, b);
        }
    }

    // epilogue: store hproj2 + att2 partial dots
    float s0 = 0.f, d0 = 0.f, s1 = 0.f, d1 = 0.f;
    int n0 = nbase + r0, n1 = n0 + 8;
    #pragma unroll
    for (int nt = 0; nt < 2; nt++) {
        int col = nq*16 + nt*8 + 2*c;
        *(float2*)&g_hproj2[n0*64 + col] = make_float2(acc[nt][0], acc[nt][1]);
        *(float2*)&g_hproj2[n1*64 + col] = make_float2(acc[nt][2], acc[nt][3]);
        s0 += acc[nt][0]*sAs[col] + acc[nt][1]*sAs[col+1];
        d0 += acc[nt][0]*sAd[col] + acc[nt][1]*sAd[col+1];
        s1 += acc[nt][2]*sAs[col] + acc[nt][3]*sAs[col+1];
        d1 += acc[nt][2]*sAd[col] + acc[nt][3]*sAd[col+1];
    }
    #pragma unroll
    for (int m = 1; m < 4; m <<= 1) {
        s0 += __shfl_xor_sync(~0u, s0, m);
        d0 += __shfl_xor_sync(~0u, d0, m);
        s1 += __shfl_xor_sync(~0u, s1, m);
        d1 += __shfl_xor_sync(~0u, d1, m);
    }
    if (c == 0) {
        sS[r0*4 + nq] = s0; sD[r0*4 + nq] = d0;
        sS[(r0+8)*4 + nq] = s1; sD[(r0+8)*4 + nq] = d1;
    }
    __syncthreads();
    if (t < P2N) {
        float ss = sS[t*4] + sS[t*4+1] + sS[t*4+2] + sS[t*4+3];
        float dd = sD[t*4] + sD[t*4+1] + sD[t*4+2] + sD[t*4+3];
        g_asrc2[nbase + t] = ss;
        g_adst2[nbase + t] = dd;
    }
}

// 8 threads/edge, 2 edges per thread: denom += ex; accum2[dst] += ex*hproj2[src]
__global__ void k_esum2(const int* __restrict__ ei) {
    int gt = blockIdx.x*blockDim.x + threadIdx.x;
    int e0 = gt >> 3, q = gt & 7;
    if (e0 >= EHALF) return;
    #pragma unroll
    for (int rep = 0; rep < 2; rep++) {
        int e = e0 + rep*EHALF;
        int s, d;
        if (e < N_EDGES) { s = ei[e]; d = ei[N_EDGES + e]; } else { s = d = e - N_EDGES; }
        float ex = expf(lrelu(g_asrc2[s] + g_adst2[d]));
        if (q == 0) atomicAdd(&g_denom2[d], ex);
        int c = q*8;
        float4 v1 = *(const float4*)&g_hproj2[s*64 + c];
        float4 v2 = *(const float4*)&g_hproj2[s*64 + c + 4];
        redAdd4(&g_accum2[d*64 + c],     v1.x*ex, v1.y*ex, v1.z*ex, v1.w*ex);
        redAdd4(&g_accum2[d*64 + c + 4], v2.x*ex, v2.y*ex, v2.z*ex, v2.w*ex);
    }
}

// fused: h2 staged once as tf32; xgates = h2@Wih^T + biases via tf32 MMA (scattered rows).
#define XGN 32
#define H2STR 68           // (4r + k) % 32 -> conflict-free A frags
__global__ void __launch_bounds__(256, 4) k_xgates2(
        const float* __restrict__ bih, const float* __restrict__ bhh,
        const float* __restrict__ b2, const float* __restrict__ g2,
        const float* __restrict__ be2,
        const int* __restrict__ batch, const int* __restrict__ ntime) {
    extern __shared__ float sm[];
    float* h2s   = sm;                    // [32][68] tf32 bits
    float* sBias = h2s + XGN*H2STR;       // 256
    float* sA2   = sBias + 256;           // 64
    float* sC2   = sA2 + 64;              // 64
    float* sInv  = sC2 + 64;              // 32
    int t = threadIdx.x;
    int nbase = blockIdx.x * XGN;

    sBias[t] = bih[t] + bhh[t];
    if (t < 64) {
        float A = g2[t]*BN_INV;
        sA2[t] = A;
        sC2[t] = A*b2[t] + be2[t];
    } else if (t >= 128 && t < 160) {
        sInv[t-128] = 1.f / g_denom2[nbase + (t-128)];
    }
    __syncthreads();

    for (int i = t; i < XGN*64; i += 256) {
        int nn = i >> 6, k = i & 63;
        float v = g_accum2[(nbase + nn)*64 + k] * sInv[nn];
        h2s[nn*H2STR + k] = __uint_as_float(f2tf32(eluf(v*sA2[k] + sC2[k])));
    }
    __syncthreads();

    const uint32_t* h2u = (const uint32_t*)h2s;
    int w = t >> 5, l = t & 31;
    int g = l >> 2, c = l & 3;
    int mt = w & 1, nh = w >> 1;   // nh in 0..3: 64-col group
    int r0 = mt*16 + g;

    float acc[8][4];
    #pragma unroll
    for (int nt = 0; nt < 8; nt++) { acc[nt][0]=0; acc[nt][1]=0; acc[nt][2]=0; acc[nt][3]=0; }

    const uint32_t* ap = h2u + r0*H2STR + c;
    #pragma unroll
    for (int ks = 0; ks < 8; ks++) {
        int kb = ks*8;
        uint32_t a[4];
        a[0] = ap[kb];
        a[1] = ap[kb + 8*H2STR];
        a[2] = ap[kb + 4];
        a[3] = ap[kb + 8*H2STR + 4];
        const uint32_t* bp0 = &g_WihT[(kb + c)*256 + nh*64 + g];
        const uint32_t* bp1 = bp0 + 4*256;
        #pragma unroll
        for (int nt = 0; nt < 8; nt++) {
            uint32_t b[2];
            b[0] = __ldg(&bp0[nt*8]);
            b[1] = __ldg(&bp1[nt*8]);
            mma_tf32(acc[nt], a, b);
        }
    }

    int n0 = nbase + r0, n1 = n0 + 8;
    int d0 = (ntime[n0]*G_GRAPHS + batch[n0])*C1;
    int d1 = (ntime[n1]*G_GRAPHS + batch[n1])*C1;
    #pragma unroll
    for (int nt = 0; nt < 8; nt++) {
        int col = nh*64 + nt*8 + 2*c;
        float bx = sBias[col], by = sBias[col+1];
        *(float2*)&g_xgates[d0 + col] = make_float2(acc[nt][0] + bx, acc[nt][1] + by);
        *(float2*)&g_xgates[d1 + col] = make_float2(acc[nt][2] + bx, acc[nt][3] + by);
    }
}

// LSTM: 1 graph/block (512 blocks), Whh row in regs, xgates prefetch, fused FC.
__global__ void __launch_bounds__(256) k_lstm(
        const float* __restrict__ Whh, const float* __restrict__ Wfc,
        const float* __restrict__ bfc, float* __restrict__ out) {
    __shared__ float hhs[64];
    __shared__ float gates[C1];
    int t = threadIdx.x;
    int g = blockIdx.x;

    unsigned long long w2[32];
    const float4* wrow = (const float4*)(Whh + t*64);
    #pragma unroll
    for (int i = 0; i < 16; i++) {
        float4 w = wrow[i];
        w2[2*i]   = pk(w.x, w.y);
        w2[2*i+1] = pk(w.z, w.w);
    }
    if (t < 64) hhs[t] = 0.f;
    float c = 0.f;
    float xg_cur = g_xgates[g*C1 + t];
    __syncthreads();

    for (int step = 0; step < T_STEPS; step++) {
        float xg_next = 0.f;
        if (step + 1 < T_STEPS) xg_next = g_xgates[((step+1)*G_GRAPHS + g)*C1 + t];
        unsigned long long aA = 0ull, aB = 0ull;
        #pragma unroll
        for (int k2 = 0; k2 < 16; k2++) {
            ulonglong2 hv = *(const ulonglong2*)&hhs[k2*4];
            ffma2(aA, hv.x, w2[2*k2]);
            ffma2(aB, hv.y, w2[2*k2+1]);
        }
        float2 a = unpk(aA), b = unpk(aB);
        gates[t] = xg_cur + a.x + a.y + b.x + b.y;
        __syncthreads();
        if (t < 64) {
            float ig = gates[t],       fg = gates[64 + t];
            float gg = gates[128 + t], og = gates[192 + t];
            c = sigf(fg)*c + sigf(ig)*tanhf(gg);
            hhs[t] = sigf(og)*tanhf(c);
        }
        __syncthreads();
        xg_cur = xg_next;
    }
    if (t < OUT_DIM) {
        float acc = bfc[t];
        #pragma unroll 8
        for (int k = 0; k < 64; k++) acc += hhs[k] * Wfc[k*OUT_DIM + t];
        out[g*OUT_DIM + t] = acc;
    }
}

// ---------------- launch ----------------
static const int SMEM_P2 = (2048 + P2N*H1STR + 64 + 64 + 128 + 128) * 4;   // 43008 B
static const int SMEM_XG = (XGN*H2STR + 256 + 64 + 64 + 32) * 4;           // 10368 B

extern "C" void kernel_launch(void* const* d_in, const int* in_sizes, int n_in,
                              void* d_out, int out_size) {
    const float* x    = (const float*)d_in[0];
    const int*   ei   = (const int*)  d_in[1];
    const int*   batch= (const int*)  d_in[2];
    const int*   ntime= (const int*)  d_in[3];
    const float* W1   = (const float*)d_in[4];
    const float* as1  = (const float*)d_in[5];
    const float* ad1  = (const float*)d_in[6];
    const float* b1   = (const float*)d_in[7];
    const float* g1   = (const float*)d_in[8];
    const float* be1  = (const float*)d_in[9];
    const float* W2   = (const float*)d_in[10];
    const float* as2  = (const float*)d_in[11];
    const float* ad2  = (const float*)d_in[12];
    const float* b2   = (const float*)d_in[13];
    const float* g2   = (const float*)d_in[14];
    const float* be2  = (const float*)d_in[15];
    const float* Wih  = (const float*)d_in[16];
    const float* Whh  = (const float*)d_in[17];
    const float* bih  = (const float*)d_in[18];
    const float* bhh  = (const float*)d_in[19];
    const float* Wfc  = (const float*)d_in[20];
    const float* bfc  = (const float*)d_in[21];
    float* out = (float*)d_out;

    cudaFuncSetAttribute(k_proj2f,  cudaFuncAttributeMaxDynamicSharedMemorySize, SMEM_P2);
    cudaFuncSetAttribute(k_xgates2, cudaFuncAttributeMaxDynamicSharedMemorySize, SMEM_XG);

    void *p_xagg, *p_acc2, *p_den2;
    cudaGetSymbolAddress(&p_xagg, g_xagg);
    cudaGetSymbolAddress(&p_acc2, g_accum2);
    cudaGetSymbolAddress(&p_den2, g_denom2);
    cudaMemsetAsync(p_xagg, 0, sizeof(float)*N_NODES*32);
    cudaMemsetAsync(p_acc2, 0, sizeof(float)*N_NODES*HID);
    cudaMemsetAsync(p_den2, 0, sizeof(float)*N_NODES);

    k_prep   <<<64, 256>>>(W1, as1, ad1, W2, Wih);         // launch 1
    k_att1   <<<(N_NODES + 255)/256, 256>>>(x);            // launch 2
    k_esum1  <<<(EHALF + 255)/256, 256>>>(ei);             // launch 3
    k_proj2f <<<N_NODES/P2N, 256, SMEM_P2>>>(W1, b1, g1, be1, as2, ad2);  // launch 4 (profiled)
    k_esum2  <<<(EHALF*8 + 255)/256, 256>>>(ei);
    k_xgates2<<<N_NODES/XGN, 256, SMEM_XG>>>(bih, bhh, b2, g2, be2, batch, ntime);
    k_lstm   <<<G_GRAPHS, 256>>>(Whh, Wfc, bfc, out);
}

// round 14
// speedup vs baseline: 1.5343x; 1.0619x over previous
#include <cuda_runtime.h>
#include <math.h>
#include <stdint.h>

#define N_NODES 25600
#define N_EDGES 204800
#define ETOT    (N_EDGES + N_NODES)   // 230400
#define EHALF   (ETOT/2)              // 115200
#define IN_CH   6
#define HID     64
#define HEADS   4
#define C1      (HEADS*HID)           // 256
#define G_GRAPHS 512
#define T_STEPS  50
#define OUT_DIM  30
#define NEG_SLOPE 0.2f
#define BN_INV 0.9999950000374996f    // 1/sqrt(1+1e-5)

// ---------------- scratch ----------------
__device__ float g_wsrc[24];
__device__ float g_wdst[24];
__device__ __align__(16) float g_x8[N_NODES*8];
__device__ __align__(16) float g_asrc1[N_NODES*4];
__device__ __align__(16) float g_adst1[N_NODES*4];
__device__ __align__(16) float g_xagg[N_NODES*32];    // 4 heads x [x0..x5, denom, 0]
__device__ __align__(16) float g_hproj2[N_NODES*HID];
__device__ float g_asrc2[N_NODES];
__device__ float g_adst2[N_NODES];
__device__ float g_denom2[N_NODES];
__device__ __align__(16) float g_accum2[N_NODES*HID];
__device__ __align__(16) float g_xgates[N_NODES*C1];  // (t, g, 256)
__device__ __align__(16) uint32_t g_W2t[256*64];      // tf32 bits, [k][j]
__device__ __align__(16) uint32_t g_WihT[64*256];     // tf32 bits, [k][j] (Wih^T)

// ---------------- helpers ----------------
__device__ __forceinline__ float lrelu(float v) { return v > 0.f ? v : NEG_SLOPE*v; }
__device__ __forceinline__ float eluf(float v)  { return v > 0.f ? v : (__expf(v) - 1.f); }
__device__ __forceinline__ float sigf(float v)  { return 1.f/(1.f+expf(-v)); }

__device__ __forceinline__ void redAdd4(float* addr, float a, float b, float c, float d) {
    asm volatile("red.global.add.v4.f32 [%0], {%1,%2,%3,%4};"
                 :: "l"(addr), "f"(a), "f"(b), "f"(c), "f"(d) : "memory");
}
__device__ __forceinline__ void ffma2(unsigned long long& d, unsigned long long a,
                                      unsigned long long b) {
    asm("fma.rn.f32x2 %0, %1, %2, %0;" : "+l"(d) : "l"(a), "l"(b));
}
__device__ __forceinline__ unsigned long long pk(float a, float b) {
    unsigned long long r;
    asm("mov.b64 %0, {%1, %2};" : "=l"(r) : "f"(a), "f"(b));
    return r;
}
__device__ __forceinline__ float2 unpk(unsigned long long v) {
    float2 r;
    asm("mov.b64 {%0, %1}, %2;" : "=f"(r.x), "=f"(r.y) : "l"(v));
    return r;
}
__device__ __forceinline__ uint32_t f2tf32(float v) {
    uint32_t r;
    asm("cvt.rna.tf32.f32 %0, %1;" : "=r"(r) : "f"(v));
    return r;
}
// m16n8k8 tf32 MMA, fp32 accumulate (in-place)
__device__ __forceinline__ void mma_tf32(float* d, const uint32_t* a, const uint32_t* b) {
    asm("mma.sync.aligned.m16n8k8.row.col.f32.tf32.tf32.f32 "
        "{%0,%1,%2,%3},{%4,%5,%6,%7},{%8,%9},{%0,%1,%2,%3};"
        : "+f"(d[0]), "+f"(d[1]), "+f"(d[2]), "+f"(d[3])
        : "r"(a[0]), "r"(a[1]), "r"(a[2]), "r"(a[3]), "r"(b[0]), "r"(b[1]));
}

// ---------------- kernels ----------------
// merged prep: tf32 weight conversion (all blocks) + attention row-vectors (block 0)
__global__ void k_prep(const float* __restrict__ W1, const float* __restrict__ as1,
                       const float* __restrict__ ad1,
                       const float* __restrict__ W2, const float* __restrict__ Wih) {
    int i = blockIdx.x*blockDim.x + threadIdx.x;
    if (i < 16384) {
        g_W2t[i] = f2tf32(W2[i]);                  // layout already [k][64]
        int j = i >> 6, k = i & 63;                // Wih is [j][k]
        g_WihT[k*256 + j] = f2tf32(Wih[i]);        // -> [k][256]
    }
    if (blockIdx.x == 0) {
        int t = threadIdx.x;
        if (t < 24) {
            int k = t >> 2, h = t & 3;
            float s = 0.f;
            for (int c = 0; c < 64; c++) s += W1[k*C1 + h*64 + c] * as1[h*64 + c];
            g_wsrc[t] = s;
        } else if (t >= 32 && t < 56) {
            int q = t - 32, k = q >> 2, h = q & 3;
            float s = 0.f;
            for (int c = 0; c < 64; c++) s += W1[k*C1 + h*64 + c] * ad1[h*64 + c];
            g_wdst[q] = s;
        }
    }
}

__global__ void k_att1(const float* __restrict__ x) {
    int n = blockIdx.x*blockDim.x + threadIdx.x;
    if (n >= N_NODES) return;
    float2 xa = *(const float2*)&x[n*6];
    float2 xb = *(const float2*)&x[n*6 + 2];
    float2 xc = *(const float2*)&x[n*6 + 4];
    float xv[6] = {xa.x, xa.y, xb.x, xb.y, xc.x, xc.y};
    float s[4] = {0,0,0,0}, d[4] = {0,0,0,0};
    #pragma unroll
    for (int k = 0; k < 6; k++) {
        #pragma unroll
        for (int h = 0; h < 4; h++) {
            s[h] += xv[k]*g_wsrc[k*4+h];
            d[h] += xv[k]*g_wdst[k*4+h];
        }
    }
    *(float4*)&g_asrc1[n*4] = make_float4(s[0],s[1],s[2],s[3]);
    *(float4*)&g_adst1[n*4] = make_float4(d[0],d[1],d[2],d[3]);
    *(float4*)&g_x8[n*8]     = make_float4(xv[0],xv[1],xv[2],xv[3]);
    *(float4*)&g_x8[n*8 + 4] = make_float4(xv[4],xv[5],0.f,0.f);
}

// 2 edges per thread for doubled memory-level parallelism
__global__ void k_esum1(const int* __restrict__ ei) {
    int e0 = blockIdx.x*blockDim.x + threadIdx.x;
    if (e0 >= EHALF) return;
    #pragma unroll
    for (int rep = 0; rep < 2; rep++) {
        int e = e0 + rep*EHALF;
        int s, d;
        if (e < N_EDGES) { s = ei[e]; d = ei[N_EDGES + e]; } else { s = d = e - N_EDGES; }
        float4 as = *(const float4*)&g_asrc1[s*4];
        float4 ad = *(const float4*)&g_adst1[d*4];
        float ex[4];
        ex[0] = expf(lrelu(as.x + ad.x));
        ex[1] = expf(lrelu(as.y + ad.y));
        ex[2] = expf(lrelu(as.z + ad.z));
        ex[3] = expf(lrelu(as.w + ad.w));
        float4 xa = *(const float4*)&g_x8[s*8];
        float4 xb = *(const float4*)&g_x8[s*8 + 4];
        float* base = &g_xagg[d*32];
        #pragma unroll
        for (int h = 0; h < 4; h++) {
            float w = ex[h];
            redAdd4(base + h*8,     w*xa.x, w*xa.y, w*xa.z, w*xa.w);
            redAdd4(base + h*8 + 4, w*xb.x, w*xb.y, w,      0.f);
        }
    }
}

// fused GAT2 projection via tf32 MMA. 64 nodes/block, 2 m-tiles per warp,
// fully unrolled K loop (immediate offsets), B frags from L1.
#define P2N 64
#define H1STR 260          // (4r + k) % 32 -> conflict-free A frags
__global__ void __launch_bounds__(256, 2) k_proj2f(
        const float* __restrict__ W1, const float* __restrict__ b1,
        const float* __restrict__ g1, const float* __restrict__ be1,
        const float* __restrict__ as2, const float* __restrict__ ad2) {
    extern __shared__ float sm[];
    float* sW1p = sm;                      // [256][8]: {w0..w5, A, C} f32 = 2048
    float* h1s  = sW1p + 2048;             // [64][260] tf32 bits
    float* sAs  = h1s + P2N*H1STR;         // 64
    float* sAd  = sAs + 64;                // 64
    float* sS   = sAd + 64;                // 256 ([64 rows][4 nq])
    float* sD   = sS + 256;                // 256
    int t = threadIdx.x;
    int nbase = blockIdx.x * P2N;

    for (int i = t; i < 2048; i += 256) {
        int c = i >> 3, r = i & 7;
        float v;
        if (r < 6)       v = W1[r*C1 + c];
        else if (r == 6) v = g1[c]*BN_INV;
        else { float A = g1[c]*BN_INV; v = A*b1[c] + be1[c]; }
        sW1p[i] = v;
    }
    if (t < 64)            sAs[t] = as2[t];
    else if (t < 128)      sAd[t-64] = ad2[t-64];
    __syncthreads();

    // phase 1: thread (nl, q) computes h1 cols [q*64, q*64+64) of node nl
    {
        int nl = t & 63, q = t >> 6;
        int n  = nbase + nl;
        float xr[24];
        #pragma unroll
        for (int h = 0; h < 4; h++) {
            float4 v0 = *(const float4*)&g_xagg[n*32 + h*8];
            float4 v1 = *(const float4*)&g_xagg[n*32 + h*8 + 4];
            float inv = 1.f / v1.z;
            xr[h*6+0] = v0.x*inv; xr[h*6+1] = v0.y*inv; xr[h*6+2] = v0.z*inv;
            xr[h*6+3] = v0.w*inv; xr[h*6+4] = v1.x*inv; xr[h*6+5] = v1.y*inv;
        }
        int h = q;                       // cols [q*64,(q+1)*64) all belong to head q
        float x0 = xr[h*6+0], x1 = xr[h*6+1], x2 = xr[h*6+2];
        float x3 = xr[h*6+3], x4 = xr[h*6+4], x5 = xr[h*6+5];
        #pragma unroll 8
        for (int c2 = 0; c2 < 64; c2++) {
            int c = q*64 + c2;
            float4 wa = *(const float4*)&sW1p[c*8];
            float4 wb = *(const float4*)&sW1p[c*8 + 4];
            float dot = x0*wa.x + x1*wa.y + x2*wa.z + x3*wa.w + x4*wb.x + x5*wb.y;
            h1s[nl*H1STR + c] = __uint_as_float(f2tf32(eluf(dot*wb.z + wb.w)));
        }
    }
    __syncthreads();

    // phase 2: MMA. warp w: mt=w&1 -> rows {mt*16, mt*16+32}; nq=w>>1 (16 cols)
    const uint32_t* h1u = (const uint32_t*)h1s;
    int w = t >> 5, l = t & 31;
    int g = l >> 2, c = l & 3;
    int mt = w & 1, nq = w >> 1;
    int r0 = mt*16 + g;

    float acc[2][2][4];                 // [m][nt][4]
    #pragma unroll
    for (int m = 0; m < 2; m++)
        #pragma unroll
        for (int nt = 0; nt < 2; nt++) {
            acc[m][nt][0]=0; acc[m][nt][1]=0; acc[m][nt][2]=0; acc[m][nt][3]=0;
        }

    const uint32_t* ap0 = h1u + r0*H1STR + c;
    const uint32_t* ap1 = ap0 + 32*H1STR;
    const uint32_t* wp  = &g_W2t[c*64 + nq*16 + g];
    #pragma unroll
    for (int ks = 0; ks < 32; ks++) {
        const int kb = ks*8;
        uint32_t a0[4], a1[4];
        a0[0] = ap0[kb];
        a0[1] = ap0[kb + 8*H1STR];
        a0[2] = ap0[kb + 4];
        a0[3] = ap0[kb + 8*H1STR + 4];
        a1[0] = ap1[kb];
        a1[1] = ap1[kb + 8*H1STR];
        a1[2] = ap1[kb + 4];
        a1[3] = ap1[kb + 8*H1STR + 4];
        #pragma unroll
        for (int nt = 0; nt < 2; nt++) {
            uint32_t b[2];
            b[0] = __ldg(&wp[kb*64 + nt*8]);
            b[1] = __ldg(&wp[(kb + 4)*64 + nt*8]);
            mma_tf32(acc[0][nt], a0, b);
            mma_tf32(acc[1][nt], a1, b);
        }
    }

    // epilogue: store hproj2 + att2 partial dots (2 m-tiles x 2 rows each)
    #pragma unroll
    for (int m = 0; m < 2; m++) {
        int rr = r0 + m*32;
        float s0 = 0.f, d0 = 0.f, s1 = 0.f, d1 = 0.f;
        int n0 = nbase + rr, n1 = n0 + 8;
        #pragma unroll
        for (int nt = 0; nt < 2; nt++) {
            int col = nq*16 + nt*8 + 2*c;
            *(float2*)&g_hproj2[n0*64 + col] = make_float2(acc[m][nt][0], acc[m][nt][1]);
            *(float2*)&g_hproj2[n1*64 + col] = make_float2(acc[m][nt][2], acc[m][nt][3]);
            s0 += acc[m][nt][0]*sAs[col] + acc[m][nt][1]*sAs[col+1];
            d0 += acc[m][nt][0]*sAd[col] + acc[m][nt][1]*sAd[col+1];
            s1 += acc[m][nt][2]*sAs[col] + acc[m][nt][3]*sAs[col+1];
            d1 += acc[m][nt][2]*sAd[col] + acc[m][nt][3]*sAd[col+1];
        }
        #pragma unroll
        for (int mm = 1; mm < 4; mm <<= 1) {
            s0 += __shfl_xor_sync(~0u, s0, mm);
            d0 += __shfl_xor_sync(~0u, d0, mm);
            s1 += __shfl_xor_sync(~0u, s1, mm);
            d1 += __shfl_xor_sync(~0u, d1, mm);
        }
        if (c == 0) {
            sS[rr*4 + nq] = s0;     sD[rr*4 + nq] = d0;
            sS[(rr+8)*4 + nq] = s1; sD[(rr+8)*4 + nq] = d1;
        }
    }
    __syncthreads();
    if (t < P2N) {
        float ss = sS[t*4] + sS[t*4+1] + sS[t*4+2] + sS[t*4+3];
        float dd = sD[t*4] + sD[t*4+1] + sD[t*4+2] + sD[t*4+3];
        g_asrc2[nbase + t] = ss;
        g_adst2[nbase + t] = dd;
    }
}

// 8 threads/edge, 2 edges per thread: denom += ex; accum2[dst] += ex*hproj2[src]
__global__ void k_esum2(const int* __restrict__ ei) {
    int gt = blockIdx.x*blockDim.x + threadIdx.x;
    int e0 = gt >> 3, q = gt & 7;
    if (e0 >= EHALF) return;
    #pragma unroll
    for (int rep = 0; rep < 2; rep++) {
        int e = e0 + rep*EHALF;
        int s, d;
        if (e < N_EDGES) { s = ei[e]; d = ei[N_EDGES + e]; } else { s = d = e - N_EDGES; }
        float ex = expf(lrelu(g_asrc2[s] + g_adst2[d]));
        if (q == 0) atomicAdd(&g_denom2[d], ex);
        int c = q*8;
        float4 v1 = *(const float4*)&g_hproj2[s*64 + c];
        float4 v2 = *(const float4*)&g_hproj2[s*64 + c + 4];
        redAdd4(&g_accum2[d*64 + c],     v1.x*ex, v1.y*ex, v1.z*ex, v1.w*ex);
        redAdd4(&g_accum2[d*64 + c + 4], v2.x*ex, v2.y*ex, v2.z*ex, v2.w*ex);
    }
}

// fused: h2 staged once as tf32; xgates = h2@Wih^T + biases via tf32 MMA (scattered rows).
#define XGN 32
#define H2STR 68           // (4r + k) % 32 -> conflict-free A frags
__global__ void __launch_bounds__(256, 4) k_xgates2(
        const float* __restrict__ bih, const float* __restrict__ bhh,
        const float* __restrict__ b2, const float* __restrict__ g2,
        const float* __restrict__ be2,
        const int* __restrict__ batch, const int* __restrict__ ntime) {
    extern __shared__ float sm[];
    float* h2s   = sm;                    // [32][68] tf32 bits
    float* sBias = h2s + XGN*H2STR;       // 256
    float* sA2   = sBias + 256;           // 64
    float* sC2   = sA2 + 64;              // 64
    float* sInv  = sC2 + 64;              // 32
    int t = threadIdx.x;
    int nbase = blockIdx.x * XGN;

    sBias[t] = bih[t] + bhh[t];
    if (t < 64) {
        float A = g2[t]*BN_INV;
        sA2[t] = A;
        sC2[t] = A*b2[t] + be2[t];
    } else if (t >= 128 && t < 160) {
        sInv[t-128] = 1.f / g_denom2[nbase + (t-128)];
    }
    __syncthreads();

    for (int i = t; i < XGN*64; i += 256) {
        int nn = i >> 6, k = i & 63;
        float v = g_accum2[(nbase + nn)*64 + k] * sInv[nn];
        h2s[nn*H2STR + k] = __uint_as_float(f2tf32(eluf(v*sA2[k] + sC2[k])));
    }
    __syncthreads();

    const uint32_t* h2u = (const uint32_t*)h2s;
    int w = t >> 5, l = t & 31;
    int g = l >> 2, c = l & 3;
    int mt = w & 1, nh = w >> 1;   // nh in 0..3: 64-col group
    int r0 = mt*16 + g;

    float acc[8][4];
    #pragma unroll
    for (int nt = 0; nt < 8; nt++) { acc[nt][0]=0; acc[nt][1]=0; acc[nt][2]=0; acc[nt][3]=0; }

    const uint32_t* ap = h2u + r0*H2STR + c;
    const uint32_t* wp = &g_WihT[c*256 + nh*64 + g];
    #pragma unroll
    for (int ks = 0; ks < 8; ks++) {
        const int kb = ks*8;
        uint32_t a[4];
        a[0] = ap[kb];
        a[1] = ap[kb + 8*H2STR];
        a[2] = ap[kb + 4];
        a[3] = ap[kb + 8*H2STR + 4];
        #pragma unroll
        for (int nt = 0; nt < 8; nt++) {
            uint32_t b[2];
            b[0] = __ldg(&wp[kb*256 + nt*8]);
            b[1] = __ldg(&wp[(kb + 4)*256 + nt*8]);
            mma_tf32(acc[nt], a, b);
        }
    }

    int n0 = nbase + r0, n1 = n0 + 8;
    int d0 = (ntime[n0]*G_GRAPHS + batch[n0])*C1;
    int d1 = (ntime[n1]*G_GRAPHS + batch[n1])*C1;
    #pragma unroll
    for (int nt = 0; nt < 8; nt++) {
        int col = nh*64 + nt*8 + 2*c;
        float bx = sBias[col], by = sBias[col+1];
        *(float2*)&g_xgates[d0 + col] = make_float2(acc[nt][0] + bx, acc[nt][1] + by);
        *(float2*)&g_xgates[d1 + col] = make_float2(acc[nt][2] + bx, acc[nt][3] + by);
    }
}

// LSTM: 1 graph/block (512 blocks), Whh row in regs, xgates prefetch, fused FC.
__global__ void __launch_bounds__(256) k_lstm(
        const float* __restrict__ Whh, const float* __restrict__ Wfc,
        const float* __restrict__ bfc, float* __restrict__ out) {
    __shared__ float hhs[64];
    __shared__ float gates[C1];
    int t = threadIdx.x;
    int g = blockIdx.x;

    unsigned long long w2[32];
    const float4* wrow = (const float4*)(Whh + t*64);
    #pragma unroll
    for (int i = 0; i < 16; i++) {
        float4 w = wrow[i];
        w2[2*i]   = pk(w.x, w.y);
        w2[2*i+1] = pk(w.z, w.w);
    }
    if (t < 64) hhs[t] = 0.f;
    float c = 0.f;
    float xg_cur = g_xgates[g*C1 + t];
    __syncthreads();

    for (int step = 0; step < T_STEPS; step++) {
        float xg_next = 0.f;
        if (step + 1 < T_STEPS) xg_next = g_xgates[((step+1)*G_GRAPHS + g)*C1 + t];
        unsigned long long aA = 0ull, aB = 0ull;
        #pragma unroll
        for (int k2 = 0; k2 < 16; k2++) {
            ulonglong2 hv = *(const ulonglong2*)&hhs[k2*4];
            ffma2(aA, hv.x, w2[2*k2]);
            ffma2(aB, hv.y, w2[2*k2+1]);
        }
        float2 a = unpk(aA), b = unpk(aB);
        gates[t] = xg_cur + a.x + a.y + b.x + b.y;
        __syncthreads();
        if (t < 64) {
            float ig = gates[t],       fg = gates[64 + t];
            float gg = gates[128 + t], og = gates[192 + t];
            c = sigf(fg)*c + sigf(ig)*tanhf(gg);
            hhs[t] = sigf(og)*tanhf(c);
        }
        __syncthreads();
        xg_cur = xg_next;
    }
    if (t < OUT_DIM) {
        float acc = bfc[t];
        #pragma unroll 8
        for (int k = 0; k < 64; k++) acc += hhs[k] * Wfc[k*OUT_DIM + t];
        out[g*OUT_DIM + t] = acc;
    }
}

// ---------------- launch ----------------
static const int SMEM_P2 = (2048 + P2N*H1STR + 64 + 64 + 256 + 256) * 4;   // 77312 B
static const int SMEM_XG = (XGN*H2STR + 256 + 64 + 64 + 32) * 4;           // 10368 B

extern "C" void kernel_launch(void* const* d_in, const int* in_sizes, int n_in,
                              void* d_out, int out_size) {
    const float* x    = (const float*)d_in[0];
    const int*   ei   = (const int*)  d_in[1];
    const int*   batch= (const int*)  d_in[2];
    const int*   ntime= (const int*)  d_in[3];
    const float* W1   = (const float*)d_in[4];
    const float* as1  = (const float*)d_in[5];
    const float* ad1  = (const float*)d_in[6];
    const float* b1   = (const float*)d_in[7];
    const float* g1   = (const float*)d_in[8];
    const float* be1  = (const float*)d_in[9];
    const float* W2   = (const float*)d_in[10];
    const float* as2  = (const float*)d_in[11];
    const float* ad2  = (const float*)d_in[12];
    const float* b2   = (const float*)d_in[13];
    const float* g2   = (const float*)d_in[14];
    const float* be2  = (const float*)d_in[15];
    const float* Wih  = (const float*)d_in[16];
    const float* Whh  = (const float*)d_in[17];
    const float* bih  = (const float*)d_in[18];
    const float* bhh  = (const float*)d_in[19];
    const float* Wfc  = (const float*)d_in[20];
    const float* bfc  = (const float*)d_in[21];
    float* out = (float*)d_out;

    cudaFuncSetAttribute(k_proj2f,  cudaFuncAttributeMaxDynamicSharedMemorySize, SMEM_P2);
    cudaFuncSetAttribute(k_xgates2, cudaFuncAttributeMaxDynamicSharedMemorySize, SMEM_XG);

    void *p_xagg, *p_acc2, *p_den2;
    cudaGetSymbolAddress(&p_xagg, g_xagg);
    cudaGetSymbolAddress(&p_acc2, g_accum2);
    cudaGetSymbolAddress(&p_den2, g_denom2);
    cudaMemsetAsync(p_xagg, 0, sizeof(float)*N_NODES*32);
    cudaMemsetAsync(p_acc2, 0, sizeof(float)*N_NODES*HID);
    cudaMemsetAsync(p_den2, 0, sizeof(float)*N_NODES);

    k_prep   <<<64, 256>>>(W1, as1, ad1, W2, Wih);         // launch 1
    k_att1   <<<(N_NODES + 255)/256, 256>>>(x);            // launch 2
    k_esum1  <<<(EHALF + 255)/256, 256>>>(ei);             // launch 3
    k_proj2f <<<N_NODES/P2N, 256, SMEM_P2>>>(W1, b1, g1, be1, as2, ad2);  // launch 4 (profiled)
    k_esum2  <<<(EHALF*8 + 255)/256, 256>>>(ei);
    k_xgates2<<<N_NODES/XGN, 256, SMEM_XG>>>(bih, bhh, b2, g2, be2, batch, ntime);
    k_lstm   <<<G_GRAPHS, 256>>>(Whh, Wfc, bfc, out);
}